// round 12
// baseline (speedup 1.0000x reference)
#include <cuda_runtime.h>
#include <cuda_bf16.h>
#include <cstdint>

#define BB 8
#define NN 1024
#define NP (BB*NN)
#define KK 20

// ---------------- scratch (device globals; no allocation allowed) -------------
__device__ float g_h1[NP*256];
__device__ float g_h2[NP*256];
__device__ float g_dist[(size_t)BB*NN*NN];
__device__ int   g_idx[NP*KK];
__device__ float g_xx[NP];
__device__ ulonglong2 g_w1p[131072];         // fp32-packed W1 pairs, per-layer offsets
__device__ float4     g_wdp[12288];          // packed (W2 - W1), per-layer offsets
__device__ uint2 g_wp2[256*64];              // W1 split (hi,lo) L3, [o][c2]
__device__ uint2 g_hp[NP*64];                // h split (hi,lo) L2-out, [p][c2]
__device__ float g_base[(size_t)NP*256];     // (W2-W1)*ctr per (p,o), L3
__device__ float g_fused[(size_t)NP*512];
__device__ uint32_t g_fh[(size_t)NP*256];    // normalized fused bf16-hi pairs
__device__ uint32_t g_fl[(size_t)NP*256];    // normalized fused bf16-lo pairs
__device__ float g_psum[(size_t)NP*256];     // transposed: [o*P + p]
__device__ float g_pssq[(size_t)NP*256];
__device__ float g_scale[1024];
__device__ float g_shift[1024];
__device__ __nv_bfloat16 g_bh[1024*512];     // Wf split hi
__device__ __nv_bfloat16 g_bl[1024*512];     // Wf split lo

__device__ __forceinline__ void fma2(unsigned long long& d,
                                     unsigned long long a, unsigned long long b) {
    asm("fma.rn.f32x2 %0, %1, %2, %0;" : "+l"(d) : "l"(a), "l"(b));
}
__device__ __forceinline__ unsigned long long pack2(float lo, float hi) {
    unsigned long long r;
    asm("mov.b64 %0, {%1, %2};" : "=l"(r) : "f"(lo), "f"(hi));
    return r;
}
__device__ __forceinline__ void unpack2(float& lo, float& hi, unsigned long long v) {
    asm("mov.b64 {%0, %1}, %2;" : "=f"(lo), "=f"(hi) : "l"(v));
}
__device__ __forceinline__ uint32_t packbf2(float a, float b) {
    __nv_bfloat162 p;
    p.x = __float2bfloat16(a);
    p.y = __float2bfloat16(b);
    return *(uint32_t*)&p;
}
// HMMA m16n8k16 bf16 -> fp32 accumulate
__device__ __forceinline__ void mma16816(float* c, const uint32_t* a, const uint32_t* b) {
    asm volatile("mma.sync.aligned.m16n8k16.row.col.f32.bf16.bf16.f32 "
        "{%0,%1,%2,%3}, {%4,%5,%6,%7}, {%8,%9}, {%0,%1,%2,%3};"
        : "+f"(c[0]), "+f"(c[1]), "+f"(c[2]), "+f"(c[3])
        : "r"(a[0]), "r"(a[1]), "r"(a[2]), "r"(a[3]), "r"(b[0]), "r"(b[1]));
}

// layer offsets into g_wdp / g_w1p (entries)
#define WOFF0 0
#define WOFF1 64
#define WOFF2 1088
#define WOFF3 3136

// ---------------- unified weight prep: wtrans(all layers) + wsplit + wfsplit ---
__global__ void prep_kernel(const float* __restrict__ W0, const float* __restrict__ W1,
                            const float* __restrict__ W2, const float* __restrict__ W3,
                            const float* __restrict__ Wf) {
    int i = blockIdx.x*256 + threadIdx.x;
    if (i < 11328) {
        const float* W; int C, OUT, base;
        if (i < 64)        { W = W0; C = 3;   OUT = 64;  base = 0;    }
        else if (i < 1088) { W = W1; C = 64;  OUT = 64;  base = 64;   }
        else if (i < 3136) { W = W2; C = 64;  OUT = 128; base = 1088; }
        else               { W = W3; C = 128; OUT = 256; base = 3136; }
        int li = i - base;
        int o = li % OUT, c4 = li / OUT;
        float w1[4], wd[4];
        #pragma unroll
        for (int j = 0; j < 4; j++) {
            int c = c4*4 + j;
            if (c < C) {
                float a = W[(size_t)o*2*C + c];
                float b2 = W[(size_t)o*2*C + C + c];
                w1[j] = a; wd[j] = b2 - a;
            } else { w1[j] = 0.f; wd[j] = 0.f; }
        }
        ulonglong2 wp;
        wp.x = pack2(w1[0], w1[1]);
        wp.y = pack2(w1[2], w1[3]);
        g_w1p[i] = wp;
        g_wdp[i] = make_float4(wd[0], wd[1], wd[2], wd[3]);
    } else if (i < 27712) {
        int li = i - 11328;                 // wsplit L3: OUT=256, C=128, C2=64
        int o = li >> 6, c2 = li & 63;
        float w0 = W3[(size_t)o*256 + 2*c2];
        float w1 = W3[(size_t)o*256 + 2*c2 + 1];
        __nv_bfloat16 h0 = __float2bfloat16(w0);
        __nv_bfloat16 h1 = __float2bfloat16(w1);
        uint2 v;
        v.x = ((uint32_t)*(uint16_t*)&h1 << 16) | (uint32_t)*(uint16_t*)&h0;
        v.y = packbf2(w0 - __bfloat162float(h0), w1 - __bfloat162float(h1));
        g_wp2[li] = v;
    } else if (i < 552000) {
        int li = i - 27712;                 // wfsplit
        float w = Wf[li];
        __nv_bfloat16 h = __float2bfloat16(w);
        g_bh[li] = h;
        g_bl[li] = __float2bfloat16(w - __bfloat162float(h));
    }
}

// ---------------- ||x||^2 per point (input layer only) -------------------------
__global__ void xx_kernel(const float* __restrict__ h, int C) {
    int p = blockIdx.x;
    __shared__ float sh[64];
    float s = 0.f;
    for (int c = threadIdx.x; c < C; c += 64) {
        float v = h[(size_t)p*C + c];
        s += v*v;
    }
    sh[threadIdx.x] = s; __syncthreads();
    for (int st = 32; st > 0; st >>= 1) {
        if (threadIdx.x < st) sh[threadIdx.x] += sh[threadIdx.x + st];
        __syncthreads();
    }
    if (threadIdx.x == 0) g_xx[p] = sh[0];
}

// ---------------- neg_dist: 64x64 register-tiled GEMM + f32x2 ------------------
__global__ void __launch_bounds__(256) negdist_kernel(const float* __restrict__ h, int C) {
    __shared__ float As[16][68];
    __shared__ float Bs[16][68];
    int b  = blockIdx.z;
    int n0 = blockIdx.y * 64, m0 = blockIdx.x * 64;
    int tid = threadIdx.x;
    int tx = tid & 15, ty = tid >> 4;
    unsigned long long acc[4][2];
    #pragma unroll
    for (int i = 0; i < 4; i++) { acc[i][0] = 0ull; acc[i][1] = 0ull; }

    for (int c0 = 0; c0 < C; c0 += 16) {
        #pragma unroll
        for (int r = 0; r < 4; r++) {
            int idx = tid + r*256;
            int cc = idx & 15, n = idx >> 4;
            int c = c0 + cc;
            As[cc][n] = (c < C) ? h[((size_t)(b*NN) + n0 + n)*C + c] : 0.f;
            Bs[cc][n] = (c < C) ? h[((size_t)(b*NN) + m0 + n)*C + c] : 0.f;
        }
        __syncthreads();
        #pragma unroll
        for (int kk = 0; kk < 16; kk++) {
            float4 a = *(const float4*)&As[kk][ty*4];
            ulonglong2 bb = *(const ulonglong2*)&Bs[kk][tx*4];
            unsigned long long a0 = pack2(a.x, a.x);
            unsigned long long a1 = pack2(a.y, a.y);
            unsigned long long a2 = pack2(a.z, a.z);
            unsigned long long a3 = pack2(a.w, a.w);
            fma2(acc[0][0], a0, bb.x); fma2(acc[0][1], a0, bb.y);
            fma2(acc[1][0], a1, bb.x); fma2(acc[1][1], a1, bb.y);
            fma2(acc[2][0], a2, bb.x); fma2(acc[2][1], a2, bb.y);
            fma2(acc[3][0], a3, bb.x); fma2(acc[3][1], a3, bb.y);
        }
        __syncthreads();
    }
    #pragma unroll
    for (int i = 0; i < 4; i++) {
        int n = n0 + ty*4 + i;
        float xn = g_xx[b*NN + n];
        #pragma unroll
        for (int jp = 0; jp < 2; jp++) {
            float lo, hi;
            unpack2(lo, hi, acc[i][jp]);
            int m = m0 + tx*4 + jp*2;
            g_dist[((size_t)(b*NN) + n)*NN + m]     = 2.f*lo - xn - g_xx[b*NN + m];
            g_dist[((size_t)(b*NN) + n)*NN + m + 1] = 2.f*hi - xn - g_xx[b*NN + m + 1];
        }
    }
}

// ------- top-k: 2 warps per point (512 each) + exact rank merge ----------------
// Selection order identical to prior verified kernel: value desc, index asc.
__global__ void __launch_bounds__(256) topk_kernel() {
    __shared__ uint32_t skey[4][2][20];
    __shared__ uint32_t sidx[4][2][20];
    int tid = threadIdx.x, wid = tid >> 5, lane = tid & 31;
    int ptb = wid >> 1, half = wid & 1;
    int p = blockIdx.x * 4 + ptb;
    int base = half * 512;
    const float* row = g_dist + (size_t)p*NN + base;
    uint32_t u[16];
    #pragma unroll
    for (int j = 0; j < 16; j++) {
        uint32_t b = __float_as_uint(row[j*32 + lane]);
        u[j] = (b & 0x80000000u) ? ~b : (b | 0x80000000u);   // monotone, exact
    }
    uint32_t m1 = 0u, m2 = 0u; int i1 = 0, i2 = 0;
    #pragma unroll
    for (int j = 0; j < 16; j++) {
        uint32_t x = u[j];
        if (x > m1) { m2 = m1; i2 = i1; m1 = x; i1 = j; }
        else if (x > m2) { m2 = x; i2 = j; }
    }
    bool have2 = true;

    for (int k = 0; k < KK; k++) {
        uint32_t um = __reduce_max_sync(0xffffffffu, m1);
        int gi = (m1 == um) ? (i1*32 + lane) : 0x7FFFFFFF;
        int gmin = __reduce_min_sync(0xffffffffu, gi);
        if (lane == 0) {
            skey[ptb][half][k] = um;
            sidx[ptb][half][k] = base + gmin;
        }
        if (gi == gmin) {
            u[i1] = 0u;
            if (have2) { m1 = m2; i1 = i2; have2 = false; }
            else {
                uint32_t a = 0u, b2 = 0u; int ai = 0, bi = 0;
                #pragma unroll
                for (int j = 0; j < 16; j++) {
                    uint32_t x = u[j];
                    if (x > a) { b2 = a; bi = ai; a = x; ai = j; }
                    else if (x > b2) { b2 = x; bi = j; }
                }
                m1 = a; i1 = ai; m2 = b2; i2 = bi; have2 = true;
            }
        }
    }
    __syncthreads();
    // exact merge: 40 candidates per point, unique 64-bit keys, rank = global pos
    if (tid < 160) {
        int pt = tid / 40, c = tid - pt*40;
        int lst = c / 20, pos = c - lst*20;
        uint32_t key = skey[pt][lst][pos];
        uint32_t idx = sidx[pt][lst][pos];
        unsigned long long mine =
            ((unsigned long long)key << 32) | (0xFFFFFFFFu - idx);
        int rank = pos;
        int ol = 1 - lst;
        #pragma unroll
        for (int j = 0; j < 20; j++) {
            unsigned long long ok =
                ((unsigned long long)skey[pt][ol][j] << 32) |
                (0xFFFFFFFFu - sidx[pt][ol][j]);
            rank += (ok > mine);
        }
        if (rank < KK)
            g_idx[(blockIdx.x*4 + pt)*KK + rank] = (int)idx;
    }
}

// ------- base = (W2-W1)*ctr (L3): 8-point tiled GEMM ---------------------------
__global__ void __launch_bounds__(256) base_kernel(const float* __restrict__ h) {
    __shared__ float4 sctr[8][32];
    int tid = threadIdx.x;
    int pbase = blockIdx.x * 8;
    sctr[tid >> 5][tid & 31] =
        ((const float4*)h)[(size_t)(pbase + (tid >> 5))*32 + (tid & 31)];
    __syncthreads();
    int o = tid;
    float acc[8];
    #pragma unroll
    for (int pt = 0; pt < 8; pt++) acc[pt] = 0.f;
    for (int c4 = 0; c4 < 32; c4++) {
        float4 w = g_wdp[WOFF3 + c4*256 + o];
        #pragma unroll
        for (int pt = 0; pt < 8; pt++) {
            float4 cv = sctr[pt][c4];
            acc[pt] += w.x*cv.x + w.y*cv.y + w.z*cv.z + w.w*cv.w;
        }
    }
    #pragma unroll
    for (int pt = 0; pt < 8; pt++)
        g_base[(size_t)(pbase + pt)*256 + o] = acc[pt];
}

// ------- edge conv (layers 0-2): exact fp32, grouped multi-point blocks -------
__global__ void edgeconv_kernel(const float* __restrict__ h, int C, int Cp,
                                int lc, int OUT, int foff, int G, int half,
                                int wOff) {
    extern __shared__ float sm[];
    __shared__ int nb[8*KK];
    int tid = threadIdx.x;
    int gidx = tid / half;
    int t = tid - gidx*half;
    int p = blockIdx.x * G + gidx;
    int b = p >> 10;
    float* ctr  = sm + gidx * (Cp + KK*Cp);
    float* feat = ctr + Cp;

    for (int t2 = tid; t2 < G*KK; t2 += blockDim.x)
        nb[t2] = g_idx[(blockIdx.x*G + t2/KK)*KK + (t2 - (t2/KK)*KK)];
    for (int c = t; c < Cp; c += half)
        ctr[c] = (c < C) ? h[(size_t)p*C + c] : 0.f;
    __syncthreads();
    int mask = Cp - 1;
    for (int tt = t; tt < KK*Cp; tt += half) {
        int k = tt >> lc, c = tt & mask;
        feat[tt] = (c < C) ? h[((size_t)((b << 10) + nb[gidx*KK + k]))*C + c] : 0.f;
    }
    __syncthreads();

    int o0 = t, o1 = t + half;
    int C4 = Cp >> 2;
    const float4* c4p = (const float4*)ctr;
    float base0 = 0.f, base1 = 0.f;
    for (int c4 = 0; c4 < C4; c4++) {
        float4 cv = c4p[c4];
        float4 w0 = g_wdp[wOff + c4*OUT + o0];
        float4 w1 = g_wdp[wOff + c4*OUT + o1];
        base0 += w0.x*cv.x + w0.y*cv.y + w0.z*cv.z + w0.w*cv.w;
        base1 += w1.x*cv.x + w1.y*cv.y + w1.z*cv.z + w1.w*cv.w;
    }
    const ulonglong2* f2 = (const ulonglong2*)feat;
    float mx0=-1e30f, s0=0.f, q0=0.f;
    float mx1=-1e30f, s1=0.f, q1=0.f;
    #pragma unroll
    for (int kc = 0; kc < KK; kc += 10) {
        unsigned long long a0[10], a1[10];
        #pragma unroll
        for (int k = 0; k < 10; k++) { a0[k] = 0ull; a1[k] = 0ull; }
        for (int c4 = 0; c4 < C4; c4++) {
            ulonglong2 w0 = g_w1p[wOff + c4*OUT + o0];
            ulonglong2 w1 = g_w1p[wOff + c4*OUT + o1];
            #pragma unroll
            for (int k = 0; k < 10; k++) {
                ulonglong2 fv = f2[(kc+k)*C4 + c4];
                fma2(a0[k], w0.x, fv.x); fma2(a0[k], w0.y, fv.y);
                fma2(a1[k], w1.x, fv.x); fma2(a1[k], w1.y, fv.y);
            }
        }
        #pragma unroll
        for (int k = 0; k < 10; k++) {
            float lo, hi;
            unpack2(lo, hi, a0[k]);
            float y = base0 + lo + hi;
            mx0 = fmaxf(mx0, y); s0 += y; q0 += y*y;
            unpack2(lo, hi, a1[k]);
            y = base1 + lo + hi;
            mx1 = fmaxf(mx1, y); s1 += y; q1 += y*y;
        }
    }
    g_fused[(size_t)p*512 + foff + o0] = mx0;
    g_fused[(size_t)p*512 + foff + o1] = mx1;
    g_psum[(size_t)o0*NP + p] = s0; g_pssq[(size_t)o0*NP + p] = q0;
    g_psum[(size_t)o1*NP + p] = s1; g_pssq[(size_t)o1*NP + p] = q1;
}

// ------- edge conv L3 via HMMA 2-way bf16 split (3 products) ------------------
__global__ void __launch_bounds__(256) edgemma_kernel(
    int C2, int OUT, int foff, int nchunks)
{
    __shared__ uint32_t sA[2][128*18];
    __shared__ uint32_t sB[2][128*18];
    __shared__ int nb[80];

    int tid = threadIdx.x, wid = tid >> 5, lane = tid & 31;
    int g = lane >> 2, t = lane & 3;
    int wm = wid >> 2, wn = wid & 3;
    int pbase = blockIdx.x * 4;
    int obase = blockIdx.y * 128;
    int batch_off = (pbase >> 10) << 10;

    if (tid < 80) nb[tid] = g_idx[(pbase + tid/20)*KK + (tid - (tid/20)*20)];

    float acc[4][4][4];
    #pragma unroll
    for (int mi = 0; mi < 4; mi++)
        #pragma unroll
        for (int ni = 0; ni < 4; ni++)
            #pragma unroll
            for (int j = 0; j < 4; j++) acc[mi][ni][j] = 0.f;

    __syncthreads();

    for (int chunk = 0; chunk < nchunks; chunk++) {
        if (chunk > 0) __syncthreads();
        for (int i = tid; i < 2048; i += 256) {
            int row = i >> 4, kp = i & 15;
            int k = row & 31, lp = row >> 5;
            int c2 = chunk*16 + kp;
            uint2 v = make_uint2(0u, 0u);
            if (k < KK && c2 < C2)
                v = g_hp[(size_t)(batch_off + nb[lp*20 + k])*C2 + c2];
            sA[0][row*18 + kp] = v.x;
            sA[1][row*18 + kp] = v.y;
        }
        for (int i = tid; i < 2048; i += 256) {
            int row = i >> 4, kp = i & 15;
            int c2 = chunk*16 + kp;
            uint2 v = make_uint2(0u, 0u);
            if (c2 < C2)
                v = g_wp2[(size_t)(obase + row)*C2 + c2];
            sB[0][row*18 + kp] = v.x;
            sB[1][row*18 + kp] = v.y;
        }
        __syncthreads();
        #pragma unroll
        for (int ks = 0; ks < 2; ks++) {
            int kp0 = ks * 8;
            uint32_t af[2][4][4];
            #pragma unroll
            for (int a = 0; a < 2; a++)
                #pragma unroll
                for (int mi = 0; mi < 4; mi++) {
                    int r = wm*64 + mi*16 + g;
                    af[a][mi][0] = sA[a][r*18 + kp0 + t];
                    af[a][mi][1] = sA[a][(r+8)*18 + kp0 + t];
                    af[a][mi][2] = sA[a][r*18 + kp0 + 4 + t];
                    af[a][mi][3] = sA[a][(r+8)*18 + kp0 + 4 + t];
                }
            uint32_t bf[2][4][2];
            #pragma unroll
            for (int a = 0; a < 2; a++)
                #pragma unroll
                for (int ni = 0; ni < 4; ni++) {
                    int n = wn*32 + ni*8 + g;
                    bf[a][ni][0] = sB[a][n*18 + kp0 + t];
                    bf[a][ni][1] = sB[a][n*18 + kp0 + 4 + t];
                }
            #pragma unroll
            for (int mi = 0; mi < 4; mi++)
                #pragma unroll
                for (int ni = 0; ni < 4; ni++) {
                    mma16816(acc[mi][ni], af[0][mi], bf[0][ni]);
                    mma16816(acc[mi][ni], af[0][mi], bf[1][ni]);
                    mma16816(acc[mi][ni], af[1][mi], bf[0][ni]);
                }
        }
    }

    #pragma unroll
    for (int half = 0; half < 2; half++) {
        int p = pbase + wm*2 + half;
        #pragma unroll
        for (int ni = 0; ni < 4; ni++) {
            #pragma unroll
            for (int j = 0; j < 2; j++) {
                float v0 = acc[half*2][ni][j];
                float v1 = acc[half*2][ni][j+2];
                float v2 = acc[half*2+1][ni][j];
                bool ok2 = (g < 4);
                float mx = fmaxf(v0, v1);
                if (ok2) mx = fmaxf(mx, v2);
                float s = v0 + v1 + (ok2 ? v2 : 0.f);
                float q = v0*v0 + v1*v1 + (ok2 ? v2*v2 : 0.f);
                #pragma unroll
                for (int off = 4; off <= 16; off <<= 1) {
                    mx = fmaxf(mx, __shfl_xor_sync(0xffffffffu, mx, off));
                    s += __shfl_xor_sync(0xffffffffu, s, off);
                    q += __shfl_xor_sync(0xffffffffu, q, off);
                }
                if (g == 0) {
                    int o = obase + wn*32 + ni*8 + t*2 + j;
                    float b = g_base[(size_t)p*256 + o];
                    g_fused[(size_t)p*512 + foff + o] = mx + b;
                    g_psum[(size_t)o*NP + p] = s + 20.f*b;
                    g_pssq[(size_t)o*NP + p] = q + 2.f*b*s + 20.f*b*b;
                }
            }
        }
    }
}

// ---------------- per-channel BN stats (verified 256-thread version) -----------
__global__ void chanstats_kernel(const float* __restrict__ g,
                                 const float* __restrict__ bta,
                                 int P, float invM) {
    int o = blockIdx.x;
    __shared__ float ssum[256], ssq[256];
    const float* ps = g_psum + (size_t)o*P;
    const float* pq = g_pssq + (size_t)o*P;
    float s = 0.f, q = 0.f;
    for (int i = threadIdx.x; i < P; i += 256) { s += ps[i]; q += pq[i]; }
    ssum[threadIdx.x] = s; ssq[threadIdx.x] = q;
    __syncthreads();
    for (int st = 128; st > 0; st >>= 1) {
        if (threadIdx.x < st) {
            ssum[threadIdx.x] += ssum[threadIdx.x + st];
            ssq [threadIdx.x] += ssq [threadIdx.x + st];
        }
        __syncthreads();
    }
    if (threadIdx.x == 0) {
        float mean = ssum[0] * invM;
        float var  = ssq[0] * invM - mean*mean;
        float sc   = rsqrtf(var + 1e-5f) * g[o];
        g_scale[o] = sc;
        g_shift[o] = bta[o] - mean * sc;
    }
}

// -- BN + LeakyReLU; fused-value bf16 split (always); optional hnext/h-split ----
__global__ void normedge_kernel(int OUT, int foff, float* __restrict__ hnext,
                                int wantnext, int wantsplit) {
    __shared__ float sh[256];
    int p = blockIdx.x, o = threadIdx.x;
    float v = g_fused[(size_t)p*512 + foff + o] * g_scale[o] + g_shift[o];
    v = v > 0.f ? v : 0.2f*v;
    g_fused[(size_t)p*512 + foff + o] = v;
    float vo = __shfl_xor_sync(0xffffffffu, v, 1);
    if (wantnext) hnext[(size_t)p*OUT + o] = v;
    if (!(o & 1)) {
        __nv_bfloat16 h0 = __float2bfloat16(v);
        __nv_bfloat16 h1 = __float2bfloat16(vo);
        uint32_t hi = ((uint32_t)*(uint16_t*)&h1 << 16) | (uint32_t)*(uint16_t*)&h0;
        uint32_t lo = packbf2(v - __bfloat162float(h0), vo - __bfloat162float(h1));
        size_t fidx = (size_t)p*256 + ((foff + o) >> 1);
        g_fh[fidx] = hi;
        g_fl[fidx] = lo;
        if (wantsplit) {
            uint2 hv; hv.x = hi; hv.y = lo;
            g_hp[(size_t)p*(OUT/2) + (o >> 1)] = hv;
        }
    }
    sh[o] = v*v;
    __syncthreads();
    for (int st = OUT >> 1; st > 0; st >>= 1) {
        if (o < st) sh[o] += sh[o + st];
        __syncthreads();
    }
    if (o == 0 && wantnext) g_xx[p] = sh[0];
}

// ---------------- final linear via HMMA bf16-split (A pre-split) ---------------
__global__ void __launch_bounds__(256) finalmma_kernel(float* __restrict__ out) {
    __shared__ uint32_t sAh[128*18], sAl[128*18];
    __shared__ uint32_t sBh[128*18], sBl[128*18];
    __shared__ float red[2][2][128];

    int tid = threadIdx.x, wid = tid >> 5, lane = tid & 31;
    int g = lane >> 2, t = lane & 3;
    int wm = wid >> 2, wn = wid & 3;
    int pb = blockIdx.x, ob = blockIdx.y;
    int pbase = pb * 128, obase = ob * 128;

    float acc[4][4][4];
    #pragma unroll
    for (int mi = 0; mi < 4; mi++)
        #pragma unroll
        for (int ni = 0; ni < 4; ni++)
            #pragma unroll
            for (int j = 0; j < 4; j++) acc[mi][ni][j] = 0.f;

    const uint32_t* bh2 = (const uint32_t*)g_bh;
    const uint32_t* bl2 = (const uint32_t*)g_bl;

    for (int c0 = 0; c0 < 512; c0 += 32) {
        __syncthreads();
        #pragma unroll
        for (int i = tid; i < 2048; i += 256) {
            int row = i >> 4, kp = i & 15;
            size_t ai = (size_t)(pbase + row)*256 + (c0 >> 1) + kp;
            sAh[row*18 + kp] = g_fh[ai];
            sAl[row*18 + kp] = g_fl[ai];
            size_t gi = (size_t)(obase + row)*256 + (c0 >> 1) + kp;
            sBh[row*18 + kp] = bh2[gi];
            sBl[row*18 + kp] = bl2[gi];
        }
        __syncthreads();
        #pragma unroll
        for (int ks = 0; ks < 2; ks++) {
            int kp0 = ks * 8;
            uint32_t ah[4][4], al[4][4];
            #pragma unroll
            for (int mi = 0; mi < 4; mi++) {
                int r = wm*64 + mi*16 + g;
                ah[mi][0] = sAh[r*18 + kp0 + t];
                ah[mi][1] = sAh[(r+8)*18 + kp0 + t];
                ah[mi][2] = sAh[r*18 + kp0 + 4 + t];
                ah[mi][3] = sAh[(r+8)*18 + kp0 + 4 + t];
                al[mi][0] = sAl[r*18 + kp0 + t];
                al[mi][1] = sAl[(r+8)*18 + kp0 + t];
                al[mi][2] = sAl[r*18 + kp0 + 4 + t];
                al[mi][3] = sAl[(r+8)*18 + kp0 + 4 + t];
            }
            uint32_t bh[4][2], bl[4][2];
            #pragma unroll
            for (int ni = 0; ni < 4; ni++) {
                int n = wn*32 + ni*8 + g;
                bh[ni][0] = sBh[n*18 + kp0 + t];
                bh[ni][1] = sBh[n*18 + kp0 + 4 + t];
                bl[ni][0] = sBl[n*18 + kp0 + t];
                bl[ni][1] = sBl[n*18 + kp0 + 4 + t];
            }
            #pragma unroll
            for (int mi = 0; mi < 4; mi++)
                #pragma unroll
                for (int ni = 0; ni < 4; ni++) {
                    mma16816(acc[mi][ni], ah[mi], bh[ni]);
                    mma16816(acc[mi][ni], ah[mi], bl[ni]);
                    mma16816(acc[mi][ni], al[mi], bh[ni]);
                }
        }
    }

    #pragma unroll
    for (int ni = 0; ni < 4; ni++) {
        float s0 = 0.f, s1 = 0.f, q0 = 0.f, q1 = 0.f;
        #pragma unroll
        for (int mi = 0; mi < 4; mi++) {
            float* a = acc[mi][ni];
            int row = pbase + wm*64 + mi*16 + g;
            int col = obase + wn*32 + ni*8 + t*2;
            *(float2*)&out[(size_t)row*1024 + col]     = make_float2(a[0], a[1]);
            *(float2*)&out[(size_t)(row+8)*1024 + col] = make_float2(a[2], a[3]);
            s0 += a[0] + a[2]; s1 += a[1] + a[3];
            q0 += a[0]*a[0] + a[2]*a[2];
            q1 += a[1]*a[1] + a[3]*a[3];
        }
        #pragma unroll
        for (int off = 4; off < 32; off <<= 1) {
            s0 += __shfl_xor_sync(0xffffffffu, s0, off);
            s1 += __shfl_xor_sync(0xffffffffu, s1, off);
            q0 += __shfl_xor_sync(0xffffffffu, q0, off);
            q1 += __shfl_xor_sync(0xffffffffu, q1, off);
        }
        if (g == 0) {
            int colw = wn*32 + ni*8 + t*2;
            red[wm][0][colw]   = s0;
            red[wm][0][colw+1] = s1;
            red[wm][1][colw]   = q0;
            red[wm][1][colw+1] = q1;
        }
    }
    __syncthreads();
    if (tid < 128) {
        float s = red[0][0][tid] + red[1][0][tid];
        float q = red[0][1][tid] + red[1][1][tid];
        g_psum[(size_t)(obase + tid)*64 + pb] = s;
        g_pssq[(size_t)(obase + tid)*64 + pb] = q;
    }
}

// ---------------- final BN + LeakyReLU in place (float4) -----------------------
__global__ void normout_kernel(float* __restrict__ out) {
    int i = blockIdx.x*256 + threadIdx.x;
    if (i >= NP*256) return;
    int ob = (i & 255) * 4;
    float4 v = ((float4*)out)[i];
    v.x = v.x * g_scale[ob+0] + g_shift[ob+0];
    v.y = v.y * g_scale[ob+1] + g_shift[ob+1];
    v.z = v.z * g_scale[ob+2] + g_shift[ob+2];
    v.w = v.w * g_scale[ob+3] + g_shift[ob+3];
    v.x = v.x > 0.f ? v.x : 0.2f*v.x;
    v.y = v.y > 0.f ? v.y : 0.2f*v.y;
    v.z = v.z > 0.f ? v.z : 0.2f*v.z;
    v.w = v.w > 0.f ? v.w : 0.2f*v.w;
    ((float4*)out)[i] = v;
}

// ------------------------------- launcher -------------------------------------
extern "C" void kernel_launch(void* const* d_in, const int* in_sizes, int n_in,
                              void* d_out, int out_size) {
    (void)in_sizes; (void)n_in; (void)out_size;
    const float* x  = (const float*)d_in[0];
    const float* W[4]  = {(const float*)d_in[1],  (const float*)d_in[4],
                          (const float*)d_in[7],  (const float*)d_in[10]};
    const float* ga[4] = {(const float*)d_in[2],  (const float*)d_in[5],
                          (const float*)d_in[8],  (const float*)d_in[11]};
    const float* bt[4] = {(const float*)d_in[3],  (const float*)d_in[6],
                          (const float*)d_in[9],  (const float*)d_in[12]};
    const float* Wf = (const float*)d_in[13];
    const float* gf = (const float*)d_in[14];
    const float* bf = (const float*)d_in[15];
    float* out = (float*)d_out;

    float *h1, *h2;
    cudaGetSymbolAddress((void**)&h1, g_h1);
    cudaGetSymbolAddress((void**)&h2, g_h2);
    float* hn[2] = {h1, h2};

    const int Cs[4]     = {3, 64, 64, 128};
    const int Cps[4]    = {4, 64, 64, 128};
    const int lcs[4]    = {2, 6, 6, 7};
    const int OUTs[4]   = {64, 64, 128, 256};
    const int foffs[4]  = {0, 64, 128, 256};
    const int Gs[4]     = {8, 8, 4, 0};
    const int wOffs[4]  = {WOFF0, WOFF1, WOFF2, WOFF3};

    prep_kernel<<<(552000 + 255)/256, 256>>>(W[0], W[1], W[2], W[3], Wf);
    xx_kernel<<<NP, 64>>>(x, 3);

    const float* hcur = x;
    for (int i = 0; i < 4; i++) {
        int C = Cs[i], Cp = Cps[i], OUT = OUTs[i];
        negdist_kernel<<<dim3(NN/64, NN/64, BB), 256>>>(hcur, C);
        topk_kernel<<<NP/4, 256>>>();
        if (i < 3) {
            int G = Gs[i], half = OUT/2;
            size_t smem = (size_t)G * (Cp + KK*Cp) * sizeof(float);
            edgeconv_kernel<<<NP/G, G*half, smem>>>(hcur, C, Cp, lcs[i], OUT,
                                                    foffs[i], G, half, wOffs[i]);
        } else {
            base_kernel<<<NP/8, 256>>>(hcur);
            edgemma_kernel<<<dim3(NP/4, 2), 256>>>(64, OUT, foffs[i], 4);
        }
        chanstats_kernel<<<OUT, 256>>>(ga[i], bt[i], NP, 1.f/((float)NP*KK));
        int wantnext = (i < 3) ? 1 : 0;
        int wantsplit = (i == 2) ? 1 : 0;
        normedge_kernel<<<NP, OUT>>>(OUT, foffs[i], hn[i & 1], wantnext, wantsplit);
        hcur = hn[i & 1];
    }

    finalmma_kernel<<<dim3(64, 8), 256>>>(out);
    chanstats_kernel<<<1024, 256>>>(gf, bf, 64, 1.f/(float)NP);
    normout_kernel<<<(NP*256 + 255)/256, 256>>>(out);
}

// round 13
// speedup vs baseline: 1.0167x; 1.0167x over previous
#include <cuda_runtime.h>
#include <cuda_bf16.h>
#include <cstdint>

#define BB 8
#define NN 1024
#define NP (BB*NN)
#define KK 20

// ---------------- scratch (device globals; no allocation allowed) -------------
__device__ float g_h1[NP*256];
__device__ float g_h2[NP*256];
__device__ uint32_t g_dist[(size_t)BB*NN*NN];   // monotone-uint distances
__device__ int   g_idx[NP*KK];
__device__ float g_xx[NP];
__device__ ulonglong2 g_w1p[131072];         // fp32-packed W1 pairs, per-layer offsets
__device__ float4     g_wdp[12288];          // packed (W2 - W1), per-layer offsets
__device__ uint2 g_wp2[256*64];              // W1 split (hi,lo) L3, [o][c2]
__device__ uint2 g_hp[NP*64];                // h split (hi,lo) L2-out, [p][c2]
__device__ float g_base[(size_t)NP*256];     // (W2-W1)*ctr per (p,o), L3
__device__ float g_fused[(size_t)NP*512];
__device__ uint32_t g_fh[(size_t)NP*256];    // normalized fused bf16-hi pairs
__device__ uint32_t g_fl[(size_t)NP*256];    // normalized fused bf16-lo pairs
__device__ float g_psum[(size_t)NP*256];     // transposed: [o*P + p]
__device__ float g_pssq[(size_t)NP*256];
__device__ float g_scale[1024];
__device__ float g_shift[1024];
__device__ __nv_bfloat16 g_bh[1024*512];     // Wf split hi
__device__ __nv_bfloat16 g_bl[1024*512];     // Wf split lo

__device__ __forceinline__ void fma2(unsigned long long& d,
                                     unsigned long long a, unsigned long long b) {
    asm("fma.rn.f32x2 %0, %1, %2, %0;" : "+l"(d) : "l"(a), "l"(b));
}
__device__ __forceinline__ unsigned long long pack2(float lo, float hi) {
    unsigned long long r;
    asm("mov.b64 %0, {%1, %2};" : "=l"(r) : "f"(lo), "f"(hi));
    return r;
}
__device__ __forceinline__ void unpack2(float& lo, float& hi, unsigned long long v) {
    asm("mov.b64 {%0, %1}, %2;" : "=f"(lo), "=f"(hi) : "l"(v));
}
__device__ __forceinline__ uint32_t packbf2(float a, float b) {
    __nv_bfloat162 p;
    p.x = __float2bfloat16(a);
    p.y = __float2bfloat16(b);
    return *(uint32_t*)&p;
}
__device__ __forceinline__ uint32_t mono_u32(float f) {
    uint32_t b = __float_as_uint(f);
    return (b & 0x80000000u) ? ~b : (b | 0x80000000u);   // exact order-preserving
}
// HMMA m16n8k16 bf16 -> fp32 accumulate
__device__ __forceinline__ void mma16816(float* c, const uint32_t* a, const uint32_t* b) {
    asm volatile("mma.sync.aligned.m16n8k16.row.col.f32.bf16.bf16.f32 "
        "{%0,%1,%2,%3}, {%4,%5,%6,%7}, {%8,%9}, {%0,%1,%2,%3};"
        : "+f"(c[0]), "+f"(c[1]), "+f"(c[2]), "+f"(c[3])
        : "r"(a[0]), "r"(a[1]), "r"(a[2]), "r"(a[3]), "r"(b[0]), "r"(b[1]));
}

// layer offsets into g_wdp / g_w1p (entries)
#define WOFF0 0
#define WOFF1 64
#define WOFF2 1088
#define WOFF3 3136

// ---------------- unified weight prep: wtrans(all layers) + wsplit + wfsplit ---
__global__ void prep_kernel(const float* __restrict__ W0, const float* __restrict__ W1,
                            const float* __restrict__ W2, const float* __restrict__ W3,
                            const float* __restrict__ Wf) {
    int i = blockIdx.x*256 + threadIdx.x;
    if (i < 11328) {
        const float* W; int C, OUT, base;
        if (i < 64)        { W = W0; C = 3;   OUT = 64;  base = 0;    }
        else if (i < 1088) { W = W1; C = 64;  OUT = 64;  base = 64;   }
        else if (i < 3136) { W = W2; C = 64;  OUT = 128; base = 1088; }
        else               { W = W3; C = 128; OUT = 256; base = 3136; }
        int li = i - base;
        int o = li % OUT, c4 = li / OUT;
        float w1[4], wd[4];
        #pragma unroll
        for (int j = 0; j < 4; j++) {
            int c = c4*4 + j;
            if (c < C) {
                float a = W[(size_t)o*2*C + c];
                float b2 = W[(size_t)o*2*C + C + c];
                w1[j] = a; wd[j] = b2 - a;
            } else { w1[j] = 0.f; wd[j] = 0.f; }
        }
        ulonglong2 wp;
        wp.x = pack2(w1[0], w1[1]);
        wp.y = pack2(w1[2], w1[3]);
        g_w1p[i] = wp;
        g_wdp[i] = make_float4(wd[0], wd[1], wd[2], wd[3]);
    } else if (i < 27712) {
        int li = i - 11328;                 // wsplit L3: OUT=256, C=128, C2=64
        int o = li >> 6, c2 = li & 63;
        float w0 = W3[(size_t)o*256 + 2*c2];
        float w1 = W3[(size_t)o*256 + 2*c2 + 1];
        __nv_bfloat16 h0 = __float2bfloat16(w0);
        __nv_bfloat16 h1 = __float2bfloat16(w1);
        uint2 v;
        v.x = ((uint32_t)*(uint16_t*)&h1 << 16) | (uint32_t)*(uint16_t*)&h0;
        v.y = packbf2(w0 - __bfloat162float(h0), w1 - __bfloat162float(h1));
        g_wp2[li] = v;
    } else if (i < 552000) {
        int li = i - 27712;                 // wfsplit
        float w = Wf[li];
        __nv_bfloat16 h = __float2bfloat16(w);
        g_bh[li] = h;
        g_bl[li] = __float2bfloat16(w - __bfloat162float(h));
    }
}

// ---------------- ||x||^2 per point (input layer only) -------------------------
__global__ void xx_kernel(const float* __restrict__ h, int C) {
    int p = blockIdx.x;
    __shared__ float sh[64];
    float s = 0.f;
    for (int c = threadIdx.x; c < C; c += 64) {
        float v = h[(size_t)p*C + c];
        s += v*v;
    }
    sh[threadIdx.x] = s; __syncthreads();
    for (int st = 32; st > 0; st >>= 1) {
        if (threadIdx.x < st) sh[threadIdx.x] += sh[threadIdx.x + st];
        __syncthreads();
    }
    if (threadIdx.x == 0) g_xx[p] = sh[0];
}

// ----- neg_dist: 64x64 register-tiled GEMM + f32x2; stores monotone uints ------
__global__ void __launch_bounds__(256) negdist_kernel(const float* __restrict__ h, int C) {
    __shared__ float As[16][68];
    __shared__ float Bs[16][68];
    int b  = blockIdx.z;
    int n0 = blockIdx.y * 64, m0 = blockIdx.x * 64;
    int tid = threadIdx.x;
    int tx = tid & 15, ty = tid >> 4;
    unsigned long long acc[4][2];
    #pragma unroll
    for (int i = 0; i < 4; i++) { acc[i][0] = 0ull; acc[i][1] = 0ull; }

    for (int c0 = 0; c0 < C; c0 += 16) {
        #pragma unroll
        for (int r = 0; r < 4; r++) {
            int idx = tid + r*256;
            int cc = idx & 15, n = idx >> 4;
            int c = c0 + cc;
            As[cc][n] = (c < C) ? h[((size_t)(b*NN) + n0 + n)*C + c] : 0.f;
            Bs[cc][n] = (c < C) ? h[((size_t)(b*NN) + m0 + n)*C + c] : 0.f;
        }
        __syncthreads();
        #pragma unroll
        for (int kk = 0; kk < 16; kk++) {
            float4 a = *(const float4*)&As[kk][ty*4];
            ulonglong2 bb = *(const ulonglong2*)&Bs[kk][tx*4];
            unsigned long long a0 = pack2(a.x, a.x);
            unsigned long long a1 = pack2(a.y, a.y);
            unsigned long long a2 = pack2(a.z, a.z);
            unsigned long long a3 = pack2(a.w, a.w);
            fma2(acc[0][0], a0, bb.x); fma2(acc[0][1], a0, bb.y);
            fma2(acc[1][0], a1, bb.x); fma2(acc[1][1], a1, bb.y);
            fma2(acc[2][0], a2, bb.x); fma2(acc[2][1], a2, bb.y);
            fma2(acc[3][0], a3, bb.x); fma2(acc[3][1], a3, bb.y);
        }
        __syncthreads();
    }
    #pragma unroll
    for (int i = 0; i < 4; i++) {
        int n = n0 + ty*4 + i;
        float xn = g_xx[b*NN + n];
        #pragma unroll
        for (int jp = 0; jp < 2; jp++) {
            float lo, hi;
            unpack2(lo, hi, acc[i][jp]);
            int m = m0 + tx*4 + jp*2;
            float d0 = 2.f*lo - xn - g_xx[b*NN + m];
            float d1 = 2.f*hi - xn - g_xx[b*NN + m + 1];
            g_dist[((size_t)(b*NN) + n)*NN + m]     = mono_u32(d0);
            g_dist[((size_t)(b*NN) + n)*NN + m + 1] = mono_u32(d1);
        }
    }
}

// ------- top-k: warp/point on pre-transformed uints + redux.sync ---------------
// Selection order: value desc, index asc -- identical to verified R9 kernel.
__global__ void topk_kernel() {
    int lane = threadIdx.x & 31;
    int p = blockIdx.x * 8 + (threadIdx.x >> 5);
    const uint32_t* row = g_dist + (size_t)p*NN;
    uint32_t u[32];
    #pragma unroll
    for (int j = 0; j < 32; j++) u[j] = row[j*32 + lane];
    uint32_t m1 = 0u, m2 = 0u; int i1 = 0, i2 = 0;
    #pragma unroll
    for (int j = 0; j < 32; j++) {
        uint32_t x = u[j];
        if (x > m1) { m2 = m1; i2 = i1; m1 = x; i1 = j; }
        else if (x > m2) { m2 = x; i2 = j; }
    }
    bool have2 = true;

    for (int k = 0; k < KK; k++) {
        uint32_t um = __reduce_max_sync(0xffffffffu, m1);
        int gi = (m1 == um) ? (i1*32 + lane) : 0x7FFFFFFF;
        int gmin = __reduce_min_sync(0xffffffffu, gi);
        if (lane == 0) g_idx[p*KK + k] = gmin;
        if (gi == gmin) {
            u[i1] = 0u;
            if (have2) { m1 = m2; i1 = i2; have2 = false; }
            else {
                uint32_t a = 0u, b2 = 0u; int ai = 0, bi = 0;
                #pragma unroll
                for (int j = 0; j < 32; j++) {
                    uint32_t x = u[j];
                    if (x > a) { b2 = a; bi = ai; a = x; ai = j; }
                    else if (x > b2) { b2 = x; bi = j; }
                }
                m1 = a; i1 = ai; m2 = b2; i2 = bi; have2 = true;
            }
        }
    }
}

// ------- base = (W2-W1)*ctr (L3): 8-point tiled GEMM ---------------------------
__global__ void __launch_bounds__(256) base_kernel(const float* __restrict__ h) {
    __shared__ float4 sctr[8][32];
    int tid = threadIdx.x;
    int pbase = blockIdx.x * 8;
    sctr[tid >> 5][tid & 31] =
        ((const float4*)h)[(size_t)(pbase + (tid >> 5))*32 + (tid & 31)];
    __syncthreads();
    int o = tid;
    float acc[8];
    #pragma unroll
    for (int pt = 0; pt < 8; pt++) acc[pt] = 0.f;
    for (int c4 = 0; c4 < 32; c4++) {
        float4 w = g_wdp[WOFF3 + c4*256 + o];
        #pragma unroll
        for (int pt = 0; pt < 8; pt++) {
            float4 cv = sctr[pt][c4];
            acc[pt] += w.x*cv.x + w.y*cv.y + w.z*cv.z + w.w*cv.w;
        }
    }
    #pragma unroll
    for (int pt = 0; pt < 8; pt++)
        g_base[(size_t)(pbase + pt)*256 + o] = acc[pt];
}

// ------- edge conv (layers 0-2): exact fp32, grouped multi-point blocks -------
__global__ void edgeconv_kernel(const float* __restrict__ h, int C, int Cp,
                                int lc, int OUT, int foff, int G, int half,
                                int wOff) {
    extern __shared__ float sm[];
    __shared__ int nb[8*KK];
    int tid = threadIdx.x;
    int gidx = tid / half;
    int t = tid - gidx*half;
    int p = blockIdx.x * G + gidx;
    int b = p >> 10;
    float* ctr  = sm + gidx * (Cp + KK*Cp);
    float* feat = ctr + Cp;

    for (int t2 = tid; t2 < G*KK; t2 += blockDim.x)
        nb[t2] = g_idx[(blockIdx.x*G + t2/KK)*KK + (t2 - (t2/KK)*KK)];
    for (int c = t; c < Cp; c += half)
        ctr[c] = (c < C) ? h[(size_t)p*C + c] : 0.f;
    __syncthreads();
    int mask = Cp - 1;
    for (int tt = t; tt < KK*Cp; tt += half) {
        int k = tt >> lc, c = tt & mask;
        feat[tt] = (c < C) ? h[((size_t)((b << 10) + nb[gidx*KK + k]))*C + c] : 0.f;
    }
    __syncthreads();

    int o0 = t, o1 = t + half;
    int C4 = Cp >> 2;
    const float4* c4p = (const float4*)ctr;
    float base0 = 0.f, base1 = 0.f;
    for (int c4 = 0; c4 < C4; c4++) {
        float4 cv = c4p[c4];
        float4 w0 = g_wdp[wOff + c4*OUT + o0];
        float4 w1 = g_wdp[wOff + c4*OUT + o1];
        base0 += w0.x*cv.x + w0.y*cv.y + w0.z*cv.z + w0.w*cv.w;
        base1 += w1.x*cv.x + w1.y*cv.y + w1.z*cv.z + w1.w*cv.w;
    }
    const ulonglong2* f2 = (const ulonglong2*)feat;
    float mx0=-1e30f, s0=0.f, q0=0.f;
    float mx1=-1e30f, s1=0.f, q1=0.f;
    #pragma unroll
    for (int kc = 0; kc < KK; kc += 10) {
        unsigned long long a0[10], a1[10];
        #pragma unroll
        for (int k = 0; k < 10; k++) { a0[k] = 0ull; a1[k] = 0ull; }
        for (int c4 = 0; c4 < C4; c4++) {
            ulonglong2 w0 = g_w1p[wOff + c4*OUT + o0];
            ulonglong2 w1 = g_w1p[wOff + c4*OUT + o1];
            #pragma unroll
            for (int k = 0; k < 10; k++) {
                ulonglong2 fv = f2[(kc+k)*C4 + c4];
                fma2(a0[k], w0.x, fv.x); fma2(a0[k], w0.y, fv.y);
                fma2(a1[k], w1.x, fv.x); fma2(a1[k], w1.y, fv.y);
            }
        }
        #pragma unroll
        for (int k = 0; k < 10; k++) {
            float lo, hi;
            unpack2(lo, hi, a0[k]);
            float y = base0 + lo + hi;
            mx0 = fmaxf(mx0, y); s0 += y; q0 += y*y;
            unpack2(lo, hi, a1[k]);
            y = base1 + lo + hi;
            mx1 = fmaxf(mx1, y); s1 += y; q1 += y*y;
        }
    }
    g_fused[(size_t)p*512 + foff + o0] = mx0;
    g_fused[(size_t)p*512 + foff + o1] = mx1;
    g_psum[(size_t)o0*NP + p] = s0; g_pssq[(size_t)o0*NP + p] = q0;
    g_psum[(size_t)o1*NP + p] = s1; g_pssq[(size_t)o1*NP + p] = q1;
}

// ------- edge conv L3 via HMMA 2-way bf16 split (3 products) ------------------
__global__ void __launch_bounds__(256) edgemma_kernel(
    int C2, int OUT, int foff, int nchunks)
{
    __shared__ uint32_t sA[2][128*18];
    __shared__ uint32_t sB[2][128*18];
    __shared__ int nb[80];

    int tid = threadIdx.x, wid = tid >> 5, lane = tid & 31;
    int g = lane >> 2, t = lane & 3;
    int wm = wid >> 2, wn = wid & 3;
    int pbase = blockIdx.x * 4;
    int obase = blockIdx.y * 128;
    int batch_off = (pbase >> 10) << 10;

    if (tid < 80) nb[tid] = g_idx[(pbase + tid/20)*KK + (tid - (tid/20)*20)];

    float acc[4][4][4];
    #pragma unroll
    for (int mi = 0; mi < 4; mi++)
        #pragma unroll
        for (int ni = 0; ni < 4; ni++)
            #pragma unroll
            for (int j = 0; j < 4; j++) acc[mi][ni][j] = 0.f;

    __syncthreads();

    for (int chunk = 0; chunk < nchunks; chunk++) {
        if (chunk > 0) __syncthreads();
        for (int i = tid; i < 2048; i += 256) {
            int row = i >> 4, kp = i & 15;
            int k = row & 31, lp = row >> 5;
            int c2 = chunk*16 + kp;
            uint2 v = make_uint2(0u, 0u);
            if (k < KK && c2 < C2)
                v = g_hp[(size_t)(batch_off + nb[lp*20 + k])*C2 + c2];
            sA[0][row*18 + kp] = v.x;
            sA[1][row*18 + kp] = v.y;
        }
        for (int i = tid; i < 2048; i += 256) {
            int row = i >> 4, kp = i & 15;
            int c2 = chunk*16 + kp;
            uint2 v = make_uint2(0u, 0u);
            if (c2 < C2)
                v = g_wp2[(size_t)(obase + row)*C2 + c2];
            sB[0][row*18 + kp] = v.x;
            sB[1][row*18 + kp] = v.y;
        }
        __syncthreads();
        #pragma unroll
        for (int ks = 0; ks < 2; ks++) {
            int kp0 = ks * 8;
            uint32_t af[2][4][4];
            #pragma unroll
            for (int a = 0; a < 2; a++)
                #pragma unroll
                for (int mi = 0; mi < 4; mi++) {
                    int r = wm*64 + mi*16 + g;
                    af[a][mi][0] = sA[a][r*18 + kp0 + t];
                    af[a][mi][1] = sA[a][(r+8)*18 + kp0 + t];
                    af[a][mi][2] = sA[a][r*18 + kp0 + 4 + t];
                    af[a][mi][3] = sA[a][(r+8)*18 + kp0 + 4 + t];
                }
            uint32_t bf[2][4][2];
            #pragma unroll
            for (int a = 0; a < 2; a++)
                #pragma unroll
                for (int ni = 0; ni < 4; ni++) {
                    int n = wn*32 + ni*8 + g;
                    bf[a][ni][0] = sB[a][n*18 + kp0 + t];
                    bf[a][ni][1] = sB[a][n*18 + kp0 + 4 + t];
                }
            #pragma unroll
            for (int mi = 0; mi < 4; mi++)
                #pragma unroll
                for (int ni = 0; ni < 4; ni++) {
                    mma16816(acc[mi][ni], af[0][mi], bf[0][ni]);
                    mma16816(acc[mi][ni], af[0][mi], bf[1][ni]);
                    mma16816(acc[mi][ni], af[1][mi], bf[0][ni]);
                }
        }
    }

    #pragma unroll
    for (int half = 0; half < 2; half++) {
        int p = pbase + wm*2 + half;
        #pragma unroll
        for (int ni = 0; ni < 4; ni++) {
            #pragma unroll
            for (int j = 0; j < 2; j++) {
                float v0 = acc[half*2][ni][j];
                float v1 = acc[half*2][ni][j+2];
                float v2 = acc[half*2+1][ni][j];
                bool ok2 = (g < 4);
                float mx = fmaxf(v0, v1);
                if (ok2) mx = fmaxf(mx, v2);
                float s = v0 + v1 + (ok2 ? v2 : 0.f);
                float q = v0*v0 + v1*v1 + (ok2 ? v2*v2 : 0.f);
                #pragma unroll
                for (int off = 4; off <= 16; off <<= 1) {
                    mx = fmaxf(mx, __shfl_xor_sync(0xffffffffu, mx, off));
                    s += __shfl_xor_sync(0xffffffffu, s, off);
                    q += __shfl_xor_sync(0xffffffffu, q, off);
                }
                if (g == 0) {
                    int o = obase + wn*32 + ni*8 + t*2 + j;
                    float b = g_base[(size_t)p*256 + o];
                    g_fused[(size_t)p*512 + foff + o] = mx + b;
                    g_psum[(size_t)o*NP + p] = s + 20.f*b;
                    g_pssq[(size_t)o*NP + p] = q + 2.f*b*s + 20.f*b*b;
                }
            }
        }
    }
}

// ---------------- per-channel BN stats (verified 256-thread version) -----------
__global__ void chanstats_kernel(const float* __restrict__ g,
                                 const float* __restrict__ bta,
                                 int P, float invM) {
    int o = blockIdx.x;
    __shared__ float ssum[256], ssq[256];
    const float* ps = g_psum + (size_t)o*P;
    const float* pq = g_pssq + (size_t)o*P;
    float s = 0.f, q = 0.f;
    for (int i = threadIdx.x; i < P; i += 256) { s += ps[i]; q += pq[i]; }
    ssum[threadIdx.x] = s; ssq[threadIdx.x] = q;
    __syncthreads();
    for (int st = 128; st > 0; st >>= 1) {
        if (threadIdx.x < st) {
            ssum[threadIdx.x] += ssum[threadIdx.x + st];
            ssq [threadIdx.x] += ssq [threadIdx.x + st];
        }
        __syncthreads();
    }
    if (threadIdx.x == 0) {
        float mean = ssum[0] * invM;
        float var  = ssq[0] * invM - mean*mean;
        float sc   = rsqrtf(var + 1e-5f) * g[o];
        g_scale[o] = sc;
        g_shift[o] = bta[o] - mean * sc;
    }
}

// -- BN + LeakyReLU; fused-value bf16 split (always); optional hnext/h-split ----
__global__ void normedge_kernel(int OUT, int foff, float* __restrict__ hnext,
                                int wantnext, int wantsplit) {
    __shared__ float sh[256];
    int p = blockIdx.x, o = threadIdx.x;
    float v = g_fused[(size_t)p*512 + foff + o] * g_scale[o] + g_shift[o];
    v = v > 0.f ? v : 0.2f*v;
    g_fused[(size_t)p*512 + foff + o] = v;
    float vo = __shfl_xor_sync(0xffffffffu, v, 1);
    if (wantnext) hnext[(size_t)p*OUT + o] = v;
    if (!(o & 1)) {
        __nv_bfloat16 h0 = __float2bfloat16(v);
        __nv_bfloat16 h1 = __float2bfloat16(vo);
        uint32_t hi = ((uint32_t)*(uint16_t*)&h1 << 16) | (uint32_t)*(uint16_t*)&h0;
        uint32_t lo = packbf2(v - __bfloat162float(h0), vo - __bfloat162float(h1));
        size_t fidx = (size_t)p*256 + ((foff + o) >> 1);
        g_fh[fidx] = hi;
        g_fl[fidx] = lo;
        if (wantsplit) {
            uint2 hv; hv.x = hi; hv.y = lo;
            g_hp[(size_t)p*(OUT/2) + (o >> 1)] = hv;
        }
    }
    sh[o] = v*v;
    __syncthreads();
    for (int st = OUT >> 1; st > 0; st >>= 1) {
        if (o < st) sh[o] += sh[o + st];
        __syncthreads();
    }
    if (o == 0 && wantnext) g_xx[p] = sh[0];
}

// ---------------- final linear via HMMA bf16-split (A pre-split) ---------------
__global__ void __launch_bounds__(256) finalmma_kernel(float* __restrict__ out) {
    __shared__ uint32_t sAh[128*18], sAl[128*18];
    __shared__ uint32_t sBh[128*18], sBl[128*18];
    __shared__ float red[2][2][128];

    int tid = threadIdx.x, wid = tid >> 5, lane = tid & 31;
    int g = lane >> 2, t = lane & 3;
    int wm = wid >> 2, wn = wid & 3;
    int pb = blockIdx.x, ob = blockIdx.y;
    int pbase = pb * 128, obase = ob * 128;

    float acc[4][4][4];
    #pragma unroll
    for (int mi = 0; mi < 4; mi++)
        #pragma unroll
        for (int ni = 0; ni < 4; ni++)
            #pragma unroll
            for (int j = 0; j < 4; j++) acc[mi][ni][j] = 0.f;

    const uint32_t* bh2 = (const uint32_t*)g_bh;
    const uint32_t* bl2 = (const uint32_t*)g_bl;

    for (int c0 = 0; c0 < 512; c0 += 32) {
        __syncthreads();
        #pragma unroll
        for (int i = tid; i < 2048; i += 256) {
            int row = i >> 4, kp = i & 15;
            size_t ai = (size_t)(pbase + row)*256 + (c0 >> 1) + kp;
            sAh[row*18 + kp] = g_fh[ai];
            sAl[row*18 + kp] = g_fl[ai];
            size_t gi = (size_t)(obase + row)*256 + (c0 >> 1) + kp;
            sBh[row*18 + kp] = bh2[gi];
            sBl[row*18 + kp] = bl2[gi];
        }
        __syncthreads();
        #pragma unroll
        for (int ks = 0; ks < 2; ks++) {
            int kp0 = ks * 8;
            uint32_t ah[4][4], al[4][4];
            #pragma unroll
            for (int mi = 0; mi < 4; mi++) {
                int r = wm*64 + mi*16 + g;
                ah[mi][0] = sAh[r*18 + kp0 + t];
                ah[mi][1] = sAh[(r+8)*18 + kp0 + t];
                ah[mi][2] = sAh[r*18 + kp0 + 4 + t];
                ah[mi][3] = sAh[(r+8)*18 + kp0 + 4 + t];
                al[mi][0] = sAl[r*18 + kp0 + t];
                al[mi][1] = sAl[(r+8)*18 + kp0 + t];
                al[mi][2] = sAl[r*18 + kp0 + 4 + t];
                al[mi][3] = sAl[(r+8)*18 + kp0 + 4 + t];
            }
            uint32_t bh[4][2], bl[4][2];
            #pragma unroll
            for (int ni = 0; ni < 4; ni++) {
                int n = wn*32 + ni*8 + g;
                bh[ni][0] = sBh[n*18 + kp0 + t];
                bh[ni][1] = sBh[n*18 + kp0 + 4 + t];
                bl[ni][0] = sBl[n*18 + kp0 + t];
                bl[ni][1] = sBl[n*18 + kp0 + 4 + t];
            }
            #pragma unroll
            for (int mi = 0; mi < 4; mi++)
                #pragma unroll
                for (int ni = 0; ni < 4; ni++) {
                    mma16816(acc[mi][ni], ah[mi], bh[ni]);
                    mma16816(acc[mi][ni], ah[mi], bl[ni]);
                    mma16816(acc[mi][ni], al[mi], bh[ni]);
                }
        }
    }

    #pragma unroll
    for (int ni = 0; ni < 4; ni++) {
        float s0 = 0.f, s1 = 0.f, q0 = 0.f, q1 = 0.f;
        #pragma unroll
        for (int mi = 0; mi < 4; mi++) {
            float* a = acc[mi][ni];
            int row = pbase + wm*64 + mi*16 + g;
            int col = obase + wn*32 + ni*8 + t*2;
            *(float2*)&out[(size_t)row*1024 + col]     = make_float2(a[0], a[1]);
            *(float2*)&out[(size_t)(row+8)*1024 + col] = make_float2(a[2], a[3]);
            s0 += a[0] + a[2]; s1 += a[1] + a[3];
            q0 += a[0]*a[0] + a[2]*a[2];
            q1 += a[1]*a[1] + a[3]*a[3];
        }
        #pragma unroll
        for (int off = 4; off < 32; off <<= 1) {
            s0 += __shfl_xor_sync(0xffffffffu, s0, off);
            s1 += __shfl_xor_sync(0xffffffffu, s1, off);
            q0 += __shfl_xor_sync(0xffffffffu, q0, off);
            q1 += __shfl_xor_sync(0xffffffffu, q1, off);
        }
        if (g == 0) {
            int colw = wn*32 + ni*8 + t*2;
            red[wm][0][colw]   = s0;
            red[wm][0][colw+1] = s1;
            red[wm][1][colw]   = q0;
            red[wm][1][colw+1] = q1;
        }
    }
    __syncthreads();
    if (tid < 128) {
        float s = red[0][0][tid] + red[1][0][tid];
        float q = red[0][1][tid] + red[1][1][tid];
        g_psum[(size_t)(obase + tid)*64 + pb] = s;
        g_pssq[(size_t)(obase + tid)*64 + pb] = q;
    }
}

// ---------------- final BN + LeakyReLU in place (float4) -----------------------
__global__ void normout_kernel(float* __restrict__ out) {
    int i = blockIdx.x*256 + threadIdx.x;
    if (i >= NP*256) return;
    int ob = (i & 255) * 4;
    float4 v = ((float4*)out)[i];
    v.x = v.x * g_scale[ob+0] + g_shift[ob+0];
    v.y = v.y * g_scale[ob+1] + g_shift[ob+1];
    v.z = v.z * g_scale[ob+2] + g_shift[ob+2];
    v.w = v.w * g_scale[ob+3] + g_shift[ob+3];
    v.x = v.x > 0.f ? v.x : 0.2f*v.x;
    v.y = v.y > 0.f ? v.y : 0.2f*v.y;
    v.z = v.z > 0.f ? v.z : 0.2f*v.z;
    v.w = v.w > 0.f ? v.w : 0.2f*v.w;
    ((float4*)out)[i] = v;
}

// ------------------------------- launcher -------------------------------------
extern "C" void kernel_launch(void* const* d_in, const int* in_sizes, int n_in,
                              void* d_out, int out_size) {
    (void)in_sizes; (void)n_in; (void)out_size;
    const float* x  = (const float*)d_in[0];
    const float* W[4]  = {(const float*)d_in[1],  (const float*)d_in[4],
                          (const float*)d_in[7],  (const float*)d_in[10]};
    const float* ga[4] = {(const float*)d_in[2],  (const float*)d_in[5],
                          (const float*)d_in[8],  (const float*)d_in[11]};
    const float* bt[4] = {(const float*)d_in[3],  (const float*)d_in[6],
                          (const float*)d_in[9],  (const float*)d_in[12]};
    const float* Wf = (const float*)d_in[13];
    const float* gf = (const float*)d_in[14];
    const float* bf = (const float*)d_in[15];
    float* out = (float*)d_out;

    float *h1, *h2;
    cudaGetSymbolAddress((void**)&h1, g_h1);
    cudaGetSymbolAddress((void**)&h2, g_h2);
    float* hn[2] = {h1, h2};

    const int Cs[4]     = {3, 64, 64, 128};
    const int Cps[4]    = {4, 64, 64, 128};
    const int lcs[4]    = {2, 6, 6, 7};
    const int OUTs[4]   = {64, 64, 128, 256};
    const int foffs[4]  = {0, 64, 128, 256};
    const int Gs[4]     = {8, 8, 4, 0};
    const int wOffs[4]  = {WOFF0, WOFF1, WOFF2, WOFF3};

    prep_kernel<<<(552000 + 255)/256, 256>>>(W[0], W[1], W[2], W[3], Wf);
    xx_kernel<<<NP, 64>>>(x, 3);

    const float* hcur = x;
    for (int i = 0; i < 4; i++) {
        int C = Cs[i], Cp = Cps[i], OUT = OUTs[i];
        negdist_kernel<<<dim3(NN/64, NN/64, BB), 256>>>(hcur, C);
        topk_kernel<<<NP/8, 256>>>();
        if (i < 3) {
            int G = Gs[i], half = OUT/2;
            size_t smem = (size_t)G * (Cp + KK*Cp) * sizeof(float);
            edgeconv_kernel<<<NP/G, G*half, smem>>>(hcur, C, Cp, lcs[i], OUT,
                                                    foffs[i], G, half, wOffs[i]);
        } else {
            base_kernel<<<NP/8, 256>>>(hcur);
            edgemma_kernel<<<dim3(NP/4, 2), 256>>>(64, OUT, foffs[i], 4);
        }
        chanstats_kernel<<<OUT, 256>>>(ga[i], bt[i], NP, 1.f/((float)NP*KK));
        int wantnext = (i < 3) ? 1 : 0;
        int wantsplit = (i == 2) ? 1 : 0;
        normedge_kernel<<<NP, OUT>>>(OUT, foffs[i], hn[i & 1], wantnext, wantsplit);
        hcur = hn[i & 1];
    }

    finalmma_kernel<<<dim3(64, 8), 256>>>(out);
    chanstats_kernel<<<1024, 256>>>(gf, bf, 64, 1.f/(float)NP);
    normout_kernel<<<(NP*256 + 255)/256, 256>>>(out);
}

// round 14
// speedup vs baseline: 1.0199x; 1.0031x over previous
#include <cuda_runtime.h>
#include <cuda_bf16.h>
#include <cstdint>

#define BB 8
#define NN 1024
#define NP (BB*NN)
#define KK 20

// ---------------- scratch (device globals; no allocation allowed) -------------
__device__ float g_h1[NP*256];
__device__ float g_h2[NP*256];
__device__ uint32_t g_dist[(size_t)BB*NN*NN];   // monotone-uint distances
__device__ int   g_idx[NP*KK];
__device__ float g_xx[NP];
__device__ ulonglong2 g_w1p[131072];         // fp32-packed W1 pairs, per-layer offsets
__device__ float4     g_wdp[12288];          // packed (W2 - W1), per-layer offsets
__device__ uint2 g_wp2[256*64];              // W1 split (hi,lo) L3, [o][c2]
__device__ uint2 g_hp[NP*64];                // h split (hi,lo) L2-out, [p][c2]
__device__ float g_base[(size_t)NP*256];     // (W2-W1)*ctr per (p,o), L3
__device__ float g_fused[(size_t)NP*512];
__device__ uint32_t g_fh[(size_t)NP*256];    // normalized fused bf16-hi pairs
__device__ uint32_t g_fl[(size_t)NP*256];    // normalized fused bf16-lo pairs
__device__ float g_psum[(size_t)NP*256];     // transposed: [o*P + p]
__device__ float g_pssq[(size_t)NP*256];
__device__ float g_scale[1024];
__device__ float g_shift[1024];
__device__ __nv_bfloat16 g_bh[1024*512];     // Wf split hi
__device__ __nv_bfloat16 g_bl[1024*512];     // Wf split lo

__device__ __forceinline__ void fma2(unsigned long long& d,
                                     unsigned long long a, unsigned long long b) {
    asm("fma.rn.f32x2 %0, %1, %2, %0;" : "+l"(d) : "l"(a), "l"(b));
}
__device__ __forceinline__ unsigned long long pack2(float lo, float hi) {
    unsigned long long r;
    asm("mov.b64 %0, {%1, %2};" : "=l"(r) : "f"(lo), "f"(hi));
    return r;
}
__device__ __forceinline__ void unpack2(float& lo, float& hi, unsigned long long v) {
    asm("mov.b64 {%0, %1}, %2;" : "=f"(lo), "=f"(hi) : "l"(v));
}
__device__ __forceinline__ uint32_t packbf2(float a, float b) {
    __nv_bfloat162 p;
    p.x = __float2bfloat16(a);
    p.y = __float2bfloat16(b);
    return *(uint32_t*)&p;
}
__device__ __forceinline__ uint32_t mono_u32(float f) {
    uint32_t b = __float_as_uint(f);
    return (b & 0x80000000u) ? ~b : (b | 0x80000000u);   // exact order-preserving
}
// HMMA m16n8k16 bf16 -> fp32 accumulate
__device__ __forceinline__ void mma16816(float* c, const uint32_t* a, const uint32_t* b) {
    asm volatile("mma.sync.aligned.m16n8k16.row.col.f32.bf16.bf16.f32 "
        "{%0,%1,%2,%3}, {%4,%5,%6,%7}, {%8,%9}, {%0,%1,%2,%3};"
        : "+f"(c[0]), "+f"(c[1]), "+f"(c[2]), "+f"(c[3])
        : "r"(a[0]), "r"(a[1]), "r"(a[2]), "r"(a[3]), "r"(b[0]), "r"(b[1]));
}

// layer offsets into g_wdp / g_w1p (entries)
#define WOFF0 0
#define WOFF1 64
#define WOFF2 1088
#define WOFF3 3136

// ---------------- unified weight prep: wtrans(all layers) + wsplit + wfsplit ---
__global__ void prep_kernel(const float* __restrict__ W0, const float* __restrict__ W1,
                            const float* __restrict__ W2, const float* __restrict__ W3,
                            const float* __restrict__ Wf) {
    int i = blockIdx.x*256 + threadIdx.x;
    if (i < 11328) {
        const float* W; int C, OUT, base;
        if (i < 64)        { W = W0; C = 3;   OUT = 64;  base = 0;    }
        else if (i < 1088) { W = W1; C = 64;  OUT = 64;  base = 64;   }
        else if (i < 3136) { W = W2; C = 64;  OUT = 128; base = 1088; }
        else               { W = W3; C = 128; OUT = 256; base = 3136; }
        int li = i - base;
        int o = li % OUT, c4 = li / OUT;
        float w1[4], wd[4];
        #pragma unroll
        for (int j = 0; j < 4; j++) {
            int c = c4*4 + j;
            if (c < C) {
                float a = W[(size_t)o*2*C + c];
                float b2 = W[(size_t)o*2*C + C + c];
                w1[j] = a; wd[j] = b2 - a;
            } else { w1[j] = 0.f; wd[j] = 0.f; }
        }
        ulonglong2 wp;
        wp.x = pack2(w1[0], w1[1]);
        wp.y = pack2(w1[2], w1[3]);
        g_w1p[i] = wp;
        g_wdp[i] = make_float4(wd[0], wd[1], wd[2], wd[3]);
    } else if (i < 27712) {
        int li = i - 11328;                 // wsplit L3: OUT=256, C=128, C2=64
        int o = li >> 6, c2 = li & 63;
        float w0 = W3[(size_t)o*256 + 2*c2];
        float w1 = W3[(size_t)o*256 + 2*c2 + 1];
        __nv_bfloat16 h0 = __float2bfloat16(w0);
        __nv_bfloat16 h1 = __float2bfloat16(w1);
        uint2 v;
        v.x = ((uint32_t)*(uint16_t*)&h1 << 16) | (uint32_t)*(uint16_t*)&h0;
        v.y = packbf2(w0 - __bfloat162float(h0), w1 - __bfloat162float(h1));
        g_wp2[li] = v;
    } else if (i < 552000) {
        int li = i - 27712;                 // wfsplit
        float w = Wf[li];
        __nv_bfloat16 h = __float2bfloat16(w);
        g_bh[li] = h;
        g_bl[li] = __float2bfloat16(w - __bfloat162float(h));
    }
}

// ---------------- ||x||^2 per point (input layer only) -------------------------
__global__ void xx_kernel(const float* __restrict__ h, int C) {
    int p = blockIdx.x;
    __shared__ float sh[64];
    float s = 0.f;
    for (int c = threadIdx.x; c < C; c += 64) {
        float v = h[(size_t)p*C + c];
        s += v*v;
    }
    sh[threadIdx.x] = s; __syncthreads();
    for (int st = 32; st > 0; st >>= 1) {
        if (threadIdx.x < st) sh[threadIdx.x] += sh[threadIdx.x + st];
        __syncthreads();
    }
    if (threadIdx.x == 0) g_xx[p] = sh[0];
}

// ----- neg_dist: 64x64 register-tiled GEMM + f32x2; stores monotone uints ------
__global__ void __launch_bounds__(256) negdist_kernel(const float* __restrict__ h, int C) {
    __shared__ float As[16][68];
    __shared__ float Bs[16][68];
    int b  = blockIdx.z;
    int n0 = blockIdx.y * 64, m0 = blockIdx.x * 64;
    int tid = threadIdx.x;
    int tx = tid & 15, ty = tid >> 4;
    unsigned long long acc[4][2];
    #pragma unroll
    for (int i = 0; i < 4; i++) { acc[i][0] = 0ull; acc[i][1] = 0ull; }

    for (int c0 = 0; c0 < C; c0 += 16) {
        #pragma unroll
        for (int r = 0; r < 4; r++) {
            int idx = tid + r*256;
            int cc = idx & 15, n = idx >> 4;
            int c = c0 + cc;
            As[cc][n] = (c < C) ? h[((size_t)(b*NN) + n0 + n)*C + c] : 0.f;
            Bs[cc][n] = (c < C) ? h[((size_t)(b*NN) + m0 + n)*C + c] : 0.f;
        }
        __syncthreads();
        #pragma unroll
        for (int kk = 0; kk < 16; kk++) {
            float4 a = *(const float4*)&As[kk][ty*4];
            ulonglong2 bb = *(const ulonglong2*)&Bs[kk][tx*4];
            unsigned long long a0 = pack2(a.x, a.x);
            unsigned long long a1 = pack2(a.y, a.y);
            unsigned long long a2 = pack2(a.z, a.z);
            unsigned long long a3 = pack2(a.w, a.w);
            fma2(acc[0][0], a0, bb.x); fma2(acc[0][1], a0, bb.y);
            fma2(acc[1][0], a1, bb.x); fma2(acc[1][1], a1, bb.y);
            fma2(acc[2][0], a2, bb.x); fma2(acc[2][1], a2, bb.y);
            fma2(acc[3][0], a3, bb.x); fma2(acc[3][1], a3, bb.y);
        }
        __syncthreads();
    }
    #pragma unroll
    for (int i = 0; i < 4; i++) {
        int n = n0 + ty*4 + i;
        float xn = g_xx[b*NN + n];
        #pragma unroll
        for (int jp = 0; jp < 2; jp++) {
            float lo, hi;
            unpack2(lo, hi, acc[i][jp]);
            int m = m0 + tx*4 + jp*2;
            float d0 = 2.f*lo - xn - g_xx[b*NN + m];
            float d1 = 2.f*hi - xn - g_xx[b*NN + m + 1];
            uint2 dv;
            dv.x = mono_u32(d0);
            dv.y = mono_u32(d1);
            *(uint2*)&g_dist[((size_t)(b*NN) + n)*NN + m] = dv;
        }
    }
}

// ------- top-k: warp/point, lane-contiguous uint4 loads + redux.sync -----------
// Selection order: value desc, index asc -- selection-set identical to verified
// kernel (set+rank is data-layout independent; global indices preserved).
__global__ void topk_kernel() {
    int lane = threadIdx.x & 31;
    int p = blockIdx.x * 8 + (threadIdx.x >> 5);
    const uint4* row = (const uint4*)(g_dist + (size_t)p*NN) + lane*8;
    uint32_t u[32];
    #pragma unroll
    for (int j = 0; j < 8; j++) {
        uint4 v = row[j];
        u[j*4+0] = v.x; u[j*4+1] = v.y; u[j*4+2] = v.z; u[j*4+3] = v.w;
    }
    // global index of u[j] = lane*32 + j
    uint32_t m1 = 0u, m2 = 0u; int i1 = 0, i2 = 0;
    #pragma unroll
    for (int j = 0; j < 32; j++) {
        uint32_t x = u[j];
        if (x > m1) { m2 = m1; i2 = i1; m1 = x; i1 = j; }
        else if (x > m2) { m2 = x; i2 = j; }
    }
    bool have2 = true;

    for (int k = 0; k < KK; k++) {
        uint32_t um = __reduce_max_sync(0xffffffffu, m1);
        int gi = (m1 == um) ? (lane*32 + i1) : 0x7FFFFFFF;
        int gmin = __reduce_min_sync(0xffffffffu, gi);
        if (lane == 0) g_idx[p*KK + k] = gmin;
        if (gi == gmin) {
            u[i1] = 0u;
            if (have2) { m1 = m2; i1 = i2; have2 = false; }
            else {
                uint32_t a = 0u, b2 = 0u; int ai = 0, bi = 0;
                #pragma unroll
                for (int j = 0; j < 32; j++) {
                    uint32_t x = u[j];
                    if (x > a) { b2 = a; bi = ai; a = x; ai = j; }
                    else if (x > b2) { b2 = x; bi = j; }
                }
                m1 = a; i1 = ai; m2 = b2; i2 = bi; have2 = true;
            }
        }
    }
}

// ------- base = (W2-W1)*ctr (L3): 8-point tiled GEMM ---------------------------
__global__ void __launch_bounds__(256) base_kernel(const float* __restrict__ h) {
    __shared__ float4 sctr[8][32];
    int tid = threadIdx.x;
    int pbase = blockIdx.x * 8;
    sctr[tid >> 5][tid & 31] =
        ((const float4*)h)[(size_t)(pbase + (tid >> 5))*32 + (tid & 31)];
    __syncthreads();
    int o = tid;
    float acc[8];
    #pragma unroll
    for (int pt = 0; pt < 8; pt++) acc[pt] = 0.f;
    for (int c4 = 0; c4 < 32; c4++) {
        float4 w = g_wdp[WOFF3 + c4*256 + o];
        #pragma unroll
        for (int pt = 0; pt < 8; pt++) {
            float4 cv = sctr[pt][c4];
            acc[pt] += w.x*cv.x + w.y*cv.y + w.z*cv.z + w.w*cv.w;
        }
    }
    #pragma unroll
    for (int pt = 0; pt < 8; pt++)
        g_base[(size_t)(pbase + pt)*256 + o] = acc[pt];
}

// ------- edge conv (layers 0-2): exact fp32, grouped multi-point blocks -------
__global__ void edgeconv_kernel(const float* __restrict__ h, int C, int Cp,
                                int lc, int OUT, int foff, int G, int half,
                                int wOff) {
    extern __shared__ float sm[];
    __shared__ int nb[8*KK];
    int tid = threadIdx.x;
    int gidx = tid / half;
    int t = tid - gidx*half;
    int p = blockIdx.x * G + gidx;
    int b = p >> 10;
    float* ctr  = sm + gidx * (Cp + KK*Cp);
    float* feat = ctr + Cp;

    for (int t2 = tid; t2 < G*KK; t2 += blockDim.x)
        nb[t2] = g_idx[(blockIdx.x*G + t2/KK)*KK + (t2 - (t2/KK)*KK)];
    for (int c = t; c < Cp; c += half)
        ctr[c] = (c < C) ? h[(size_t)p*C + c] : 0.f;
    __syncthreads();
    int mask = Cp - 1;
    for (int tt = t; tt < KK*Cp; tt += half) {
        int k = tt >> lc, c = tt & mask;
        feat[tt] = (c < C) ? h[((size_t)((b << 10) + nb[gidx*KK + k]))*C + c] : 0.f;
    }
    __syncthreads();

    int o0 = t, o1 = t + half;
    int C4 = Cp >> 2;
    const float4* c4p = (const float4*)ctr;
    float base0 = 0.f, base1 = 0.f;
    for (int c4 = 0; c4 < C4; c4++) {
        float4 cv = c4p[c4];
        float4 w0 = g_wdp[wOff + c4*OUT + o0];
        float4 w1 = g_wdp[wOff + c4*OUT + o1];
        base0 += w0.x*cv.x + w0.y*cv.y + w0.z*cv.z + w0.w*cv.w;
        base1 += w1.x*cv.x + w1.y*cv.y + w1.z*cv.z + w1.w*cv.w;
    }
    const ulonglong2* f2 = (const ulonglong2*)feat;
    float mx0=-1e30f, s0=0.f, q0=0.f;
    float mx1=-1e30f, s1=0.f, q1=0.f;
    #pragma unroll
    for (int kc = 0; kc < KK; kc += 10) {
        unsigned long long a0[10], a1[10];
        #pragma unroll
        for (int k = 0; k < 10; k++) { a0[k] = 0ull; a1[k] = 0ull; }
        for (int c4 = 0; c4 < C4; c4++) {
            ulonglong2 w0 = g_w1p[wOff + c4*OUT + o0];
            ulonglong2 w1 = g_w1p[wOff + c4*OUT + o1];
            #pragma unroll
            for (int k = 0; k < 10; k++) {
                ulonglong2 fv = f2[(kc+k)*C4 + c4];
                fma2(a0[k], w0.x, fv.x); fma2(a0[k], w0.y, fv.y);
                fma2(a1[k], w1.x, fv.x); fma2(a1[k], w1.y, fv.y);
            }
        }
        #pragma unroll
        for (int k = 0; k < 10; k++) {
            float lo, hi;
            unpack2(lo, hi, a0[k]);
            float y = base0 + lo + hi;
            mx0 = fmaxf(mx0, y); s0 += y; q0 += y*y;
            unpack2(lo, hi, a1[k]);
            y = base1 + lo + hi;
            mx1 = fmaxf(mx1, y); s1 += y; q1 += y*y;
        }
    }
    g_fused[(size_t)p*512 + foff + o0] = mx0;
    g_fused[(size_t)p*512 + foff + o1] = mx1;
    g_psum[(size_t)o0*NP + p] = s0; g_pssq[(size_t)o0*NP + p] = q0;
    g_psum[(size_t)o1*NP + p] = s1; g_pssq[(size_t)o1*NP + p] = q1;
}

// ------- edge conv L3 via HMMA 2-way bf16 split (3 products) ------------------
__global__ void __launch_bounds__(256) edgemma_kernel(
    int C2, int OUT, int foff, int nchunks)
{
    __shared__ uint32_t sA[2][128*18];
    __shared__ uint32_t sB[2][128*18];
    __shared__ int nb[80];

    int tid = threadIdx.x, wid = tid >> 5, lane = tid & 31;
    int g = lane >> 2, t = lane & 3;
    int wm = wid >> 2, wn = wid & 3;
    int pbase = blockIdx.x * 4;
    int obase = blockIdx.y * 128;
    int batch_off = (pbase >> 10) << 10;

    if (tid < 80) nb[tid] = g_idx[(pbase + tid/20)*KK + (tid - (tid/20)*20)];

    float acc[4][4][4];
    #pragma unroll
    for (int mi = 0; mi < 4; mi++)
        #pragma unroll
        for (int ni = 0; ni < 4; ni++)
            #pragma unroll
            for (int j = 0; j < 4; j++) acc[mi][ni][j] = 0.f;

    __syncthreads();

    for (int chunk = 0; chunk < nchunks; chunk++) {
        if (chunk > 0) __syncthreads();
        for (int i = tid; i < 2048; i += 256) {
            int row = i >> 4, kp = i & 15;
            int k = row & 31, lp = row >> 5;
            int c2 = chunk*16 + kp;
            uint2 v = make_uint2(0u, 0u);
            if (k < KK && c2 < C2)
                v = g_hp[(size_t)(batch_off + nb[lp*20 + k])*C2 + c2];
            sA[0][row*18 + kp] = v.x;
            sA[1][row*18 + kp] = v.y;
        }
        for (int i = tid; i < 2048; i += 256) {
            int row = i >> 4, kp = i & 15;
            int c2 = chunk*16 + kp;
            uint2 v = make_uint2(0u, 0u);
            if (c2 < C2)
                v = g_wp2[(size_t)(obase + row)*C2 + c2];
            sB[0][row*18 + kp] = v.x;
            sB[1][row*18 + kp] = v.y;
        }
        __syncthreads();
        #pragma unroll
        for (int ks = 0; ks < 2; ks++) {
            int kp0 = ks * 8;
            uint32_t af[2][4][4];
            #pragma unroll
            for (int a = 0; a < 2; a++)
                #pragma unroll
                for (int mi = 0; mi < 4; mi++) {
                    int r = wm*64 + mi*16 + g;
                    af[a][mi][0] = sA[a][r*18 + kp0 + t];
                    af[a][mi][1] = sA[a][(r+8)*18 + kp0 + t];
                    af[a][mi][2] = sA[a][r*18 + kp0 + 4 + t];
                    af[a][mi][3] = sA[a][(r+8)*18 + kp0 + 4 + t];
                }
            uint32_t bf[2][4][2];
            #pragma unroll
            for (int a = 0; a < 2; a++)
                #pragma unroll
                for (int ni = 0; ni < 4; ni++) {
                    int n = wn*32 + ni*8 + g;
                    bf[a][ni][0] = sB[a][n*18 + kp0 + t];
                    bf[a][ni][1] = sB[a][n*18 + kp0 + 4 + t];
                }
            #pragma unroll
            for (int mi = 0; mi < 4; mi++)
                #pragma unroll
                for (int ni = 0; ni < 4; ni++) {
                    mma16816(acc[mi][ni], af[0][mi], bf[0][ni]);
                    mma16816(acc[mi][ni], af[0][mi], bf[1][ni]);
                    mma16816(acc[mi][ni], af[1][mi], bf[0][ni]);
                }
        }
    }

    #pragma unroll
    for (int half = 0; half < 2; half++) {
        int p = pbase + wm*2 + half;
        #pragma unroll
        for (int ni = 0; ni < 4; ni++) {
            #pragma unroll
            for (int j = 0; j < 2; j++) {
                float v0 = acc[half*2][ni][j];
                float v1 = acc[half*2][ni][j+2];
                float v2 = acc[half*2+1][ni][j];
                bool ok2 = (g < 4);
                float mx = fmaxf(v0, v1);
                if (ok2) mx = fmaxf(mx, v2);
                float s = v0 + v1 + (ok2 ? v2 : 0.f);
                float q = v0*v0 + v1*v1 + (ok2 ? v2*v2 : 0.f);
                #pragma unroll
                for (int off = 4; off <= 16; off <<= 1) {
                    mx = fmaxf(mx, __shfl_xor_sync(0xffffffffu, mx, off));
                    s += __shfl_xor_sync(0xffffffffu, s, off);
                    q += __shfl_xor_sync(0xffffffffu, q, off);
                }
                if (g == 0) {
                    int o = obase + wn*32 + ni*8 + t*2 + j;
                    float b = g_base[(size_t)p*256 + o];
                    g_fused[(size_t)p*512 + foff + o] = mx + b;
                    g_psum[(size_t)o*NP + p] = s + 20.f*b;
                    g_pssq[(size_t)o*NP + p] = q + 2.f*b*s + 20.f*b*b;
                }
            }
        }
    }
}

// ---------------- per-channel BN stats (verified 256-thread version) -----------
__global__ void chanstats_kernel(const float* __restrict__ g,
                                 const float* __restrict__ bta,
                                 int P, float invM) {
    int o = blockIdx.x;
    __shared__ float ssum[256], ssq[256];
    const float* ps = g_psum + (size_t)o*P;
    const float* pq = g_pssq + (size_t)o*P;
    float s = 0.f, q = 0.f;
    for (int i = threadIdx.x; i < P; i += 256) { s += ps[i]; q += pq[i]; }
    ssum[threadIdx.x] = s; ssq[threadIdx.x] = q;
    __syncthreads();
    for (int st = 128; st > 0; st >>= 1) {
        if (threadIdx.x < st) {
            ssum[threadIdx.x] += ssum[threadIdx.x + st];
            ssq [threadIdx.x] += ssq [threadIdx.x + st];
        }
        __syncthreads();
    }
    if (threadIdx.x == 0) {
        float mean = ssum[0] * invM;
        float var  = ssq[0] * invM - mean*mean;
        float sc   = rsqrtf(var + 1e-5f) * g[o];
        g_scale[o] = sc;
        g_shift[o] = bta[o] - mean * sc;
    }
}

// -- BN + LeakyReLU (grouped blocks); per-point reduction tree is bit-identical --
__global__ void normedge_kernel(int OUT, int foff, float* __restrict__ hnext,
                                int wantnext, int wantsplit, int G2) {
    __shared__ float sh[256];
    int tid = threadIdx.x;
    int gidx = tid / OUT;
    int o = tid - gidx*OUT;
    int p = blockIdx.x * G2 + gidx;
    float v = g_fused[(size_t)p*512 + foff + o] * g_scale[o] + g_shift[o];
    v = v > 0.f ? v : 0.2f*v;
    g_fused[(size_t)p*512 + foff + o] = v;
    float vo = __shfl_xor_sync(0xffffffffu, v, 1);   // o parity == lane parity (OUT%32==0)
    if (wantnext) hnext[(size_t)p*OUT + o] = v;
    if (!(o & 1)) {
        __nv_bfloat16 h0 = __float2bfloat16(v);
        __nv_bfloat16 h1 = __float2bfloat16(vo);
        uint32_t hi = ((uint32_t)*(uint16_t*)&h1 << 16) | (uint32_t)*(uint16_t*)&h0;
        uint32_t lo = packbf2(v - __bfloat162float(h0), vo - __bfloat162float(h1));
        size_t fidx = (size_t)p*256 + ((foff + o) >> 1);
        g_fh[fidx] = hi;
        g_fl[fidx] = lo;
        if (wantsplit) {
            uint2 hv; hv.x = hi; hv.y = lo;
            g_hp[(size_t)p*(OUT/2) + (o >> 1)] = hv;
        }
    }
    sh[tid] = v*v;
    __syncthreads();
    for (int st = OUT >> 1; st > 0; st >>= 1) {
        if (o < st) sh[tid] += sh[tid + st];
        __syncthreads();
    }
    if (o == 0 && wantnext) g_xx[p] = sh[tid];
}

// ---------------- final linear via HMMA bf16-split (A pre-split) ---------------
__global__ void __launch_bounds__(256) finalmma_kernel(float* __restrict__ out) {
    __shared__ uint32_t sAh[128*18], sAl[128*18];
    __shared__ uint32_t sBh[128*18], sBl[128*18];
    __shared__ float red[2][2][128];

    int tid = threadIdx.x, wid = tid >> 5, lane = tid & 31;
    int g = lane >> 2, t = lane & 3;
    int wm = wid >> 2, wn = wid & 3;
    int pb = blockIdx.x, ob = blockIdx.y;
    int pbase = pb * 128, obase = ob * 128;

    float acc[4][4][4];
    #pragma unroll
    for (int mi = 0; mi < 4; mi++)
        #pragma unroll
        for (int ni = 0; ni < 4; ni++)
            #pragma unroll
            for (int j = 0; j < 4; j++) acc[mi][ni][j] = 0.f;

    const uint32_t* bh2 = (const uint32_t*)g_bh;
    const uint32_t* bl2 = (const uint32_t*)g_bl;

    for (int c0 = 0; c0 < 512; c0 += 32) {
        __syncthreads();
        #pragma unroll
        for (int i = tid; i < 2048; i += 256) {
            int row = i >> 4, kp = i & 15;
            size_t ai = (size_t)(pbase + row)*256 + (c0 >> 1) + kp;
            sAh[row*18 + kp] = g_fh[ai];
            sAl[row*18 + kp] = g_fl[ai];
            size_t gi = (size_t)(obase + row)*256 + (c0 >> 1) + kp;
            sBh[row*18 + kp] = bh2[gi];
            sBl[row*18 + kp] = bl2[gi];
        }
        __syncthreads();
        #pragma unroll
        for (int ks = 0; ks < 2; ks++) {
            int kp0 = ks * 8;
            uint32_t ah[4][4], al[4][4];
            #pragma unroll
            for (int mi = 0; mi < 4; mi++) {
                int r = wm*64 + mi*16 + g;
                ah[mi][0] = sAh[r*18 + kp0 + t];
                ah[mi][1] = sAh[(r+8)*18 + kp0 + t];
                ah[mi][2] = sAh[r*18 + kp0 + 4 + t];
                ah[mi][3] = sAh[(r+8)*18 + kp0 + 4 + t];
                al[mi][0] = sAl[r*18 + kp0 + t];
                al[mi][1] = sAl[(r+8)*18 + kp0 + t];
                al[mi][2] = sAl[r*18 + kp0 + 4 + t];
                al[mi][3] = sAl[(r+8)*18 + kp0 + 4 + t];
            }
            uint32_t bh[4][2], bl[4][2];
            #pragma unroll
            for (int ni = 0; ni < 4; ni++) {
                int n = wn*32 + ni*8 + g;
                bh[ni][0] = sBh[n*18 + kp0 + t];
                bh[ni][1] = sBh[n*18 + kp0 + 4 + t];
                bl[ni][0] = sBl[n*18 + kp0 + t];
                bl[ni][1] = sBl[n*18 + kp0 + 4 + t];
            }
            #pragma unroll
            for (int mi = 0; mi < 4; mi++)
                #pragma unroll
                for (int ni = 0; ni < 4; ni++) {
                    mma16816(acc[mi][ni], ah[mi], bh[ni]);
                    mma16816(acc[mi][ni], ah[mi], bl[ni]);
                    mma16816(acc[mi][ni], al[mi], bh[ni]);
                }
        }
    }

    #pragma unroll
    for (int ni = 0; ni < 4; ni++) {
        float s0 = 0.f, s1 = 0.f, q0 = 0.f, q1 = 0.f;
        #pragma unroll
        for (int mi = 0; mi < 4; mi++) {
            float* a = acc[mi][ni];
            int row = pbase + wm*64 + mi*16 + g;
            int col = obase + wn*32 + ni*8 + t*2;
            *(float2*)&out[(size_t)row*1024 + col]     = make_float2(a[0], a[1]);
            *(float2*)&out[(size_t)(row+8)*1024 + col] = make_float2(a[2], a[3]);
            s0 += a[0] + a[2]; s1 += a[1] + a[3];
            q0 += a[0]*a[0] + a[2]*a[2];
            q1 += a[1]*a[1] + a[3]*a[3];
        }
        #pragma unroll
        for (int off = 4; off < 32; off <<= 1) {
            s0 += __shfl_xor_sync(0xffffffffu, s0, off);
            s1 += __shfl_xor_sync(0xffffffffu, s1, off);
            q0 += __shfl_xor_sync(0xffffffffu, q0, off);
            q1 += __shfl_xor_sync(0xffffffffu, q1, off);
        }
        if (g == 0) {
            int colw = wn*32 + ni*8 + t*2;
            red[wm][0][colw]   = s0;
            red[wm][0][colw+1] = s1;
            red[wm][1][colw]   = q0;
            red[wm][1][colw+1] = q1;
        }
    }
    __syncthreads();
    if (tid < 128) {
        float s = red[0][0][tid] + red[1][0][tid];
        float q = red[0][1][tid] + red[1][1][tid];
        g_psum[(size_t)(obase + tid)*64 + pb] = s;
        g_pssq[(size_t)(obase + tid)*64 + pb] = q;
    }
}

// ---------------- final BN + LeakyReLU in place (float4) -----------------------
__global__ void normout_kernel(float* __restrict__ out) {
    int i = blockIdx.x*256 + threadIdx.x;
    if (i >= NP*256) return;
    int ob = (i & 255) * 4;
    float4 v = ((float4*)out)[i];
    v.x = v.x * g_scale[ob+0] + g_shift[ob+0];
    v.y = v.y * g_scale[ob+1] + g_shift[ob+1];
    v.z = v.z * g_scale[ob+2] + g_shift[ob+2];
    v.w = v.w * g_scale[ob+3] + g_shift[ob+3];
    v.x = v.x > 0.f ? v.x : 0.2f*v.x;
    v.y = v.y > 0.f ? v.y : 0.2f*v.y;
    v.z = v.z > 0.f ? v.z : 0.2f*v.z;
    v.w = v.w > 0.f ? v.w : 0.2f*v.w;
    ((float4*)out)[i] = v;
}

// ------------------------------- launcher -------------------------------------
extern "C" void kernel_launch(void* const* d_in, const int* in_sizes, int n_in,
                              void* d_out, int out_size) {
    (void)in_sizes; (void)n_in; (void)out_size;
    const float* x  = (const float*)d_in[0];
    const float* W[4]  = {(const float*)d_in[1],  (const float*)d_in[4],
                          (const float*)d_in[7],  (const float*)d_in[10]};
    const float* ga[4] = {(const float*)d_in[2],  (const float*)d_in[5],
                          (const float*)d_in[8],  (const float*)d_in[11]};
    const float* bt[4] = {(const float*)d_in[3],  (const float*)d_in[6],
                          (const float*)d_in[9],  (const float*)d_in[12]};
    const float* Wf = (const float*)d_in[13];
    const float* gf = (const float*)d_in[14];
    const float* bf = (const float*)d_in[15];
    float* out = (float*)d_out;

    float *h1, *h2;
    cudaGetSymbolAddress((void**)&h1, g_h1);
    cudaGetSymbolAddress((void**)&h2, g_h2);
    float* hn[2] = {h1, h2};

    const int Cs[4]     = {3, 64, 64, 128};
    const int Cps[4]    = {4, 64, 64, 128};
    const int lcs[4]    = {2, 6, 6, 7};
    const int OUTs[4]   = {64, 64, 128, 256};
    const int foffs[4]  = {0, 64, 128, 256};
    const int Gs[4]     = {8, 8, 4, 0};
    const int G2s[4]    = {4, 4, 2, 1};
    const int wOffs[4]  = {WOFF0, WOFF1, WOFF2, WOFF3};

    prep_kernel<<<(552000 + 255)/256, 256>>>(W[0], W[1], W[2], W[3], Wf);
    xx_kernel<<<NP, 64>>>(x, 3);

    const float* hcur = x;
    for (int i = 0; i < 4; i++) {
        int C = Cs[i], Cp = Cps[i], OUT = OUTs[i];
        negdist_kernel<<<dim3(NN/64, NN/64, BB), 256>>>(hcur, C);
        topk_kernel<<<NP/8, 256>>>();
        if (i < 3) {
            int G = Gs[i], half = OUT/2;
            size_t smem = (size_t)G * (Cp + KK*Cp) * sizeof(float);
            edgeconv_kernel<<<NP/G, G*half, smem>>>(hcur, C, Cp, lcs[i], OUT,
                                                    foffs[i], G, half, wOffs[i]);
        } else {
            base_kernel<<<NP/8, 256>>>(hcur);
            edgemma_kernel<<<dim3(NP/4, 2), 256>>>(64, OUT, foffs[i], 4);
        }
        chanstats_kernel<<<OUT, 256>>>(ga[i], bt[i], NP, 1.f/((float)NP*KK));
        int wantnext = (i < 3) ? 1 : 0;
        int wantsplit = (i == 2) ? 1 : 0;
        int G2 = G2s[i];
        normedge_kernel<<<NP/G2, G2*OUT>>>(OUT, foffs[i], hn[i & 1],
                                           wantnext, wantsplit, G2);
        hcur = hn[i & 1];
    }

    finalmma_kernel<<<dim3(64, 8), 256>>>(out);
    chanstats_kernel<<<1024, 256>>>(gf, bf, 64, 1.f/(float)NP);
    normout_kernel<<<(NP*256 + 255)/256, 256>>>(out);
}

// round 15
// speedup vs baseline: 1.0340x; 1.0139x over previous
#include <cuda_runtime.h>
#include <cuda_bf16.h>
#include <cstdint>

#define BB 8
#define NN 1024
#define NP (BB*NN)
#define KK 20

// ---------------- scratch (device globals; no allocation allowed) -------------
__device__ float g_h1[NP*256];
__device__ float g_h2[NP*256];
__device__ uint32_t g_dist[(size_t)BB*NN*NN];   // monotone-uint distances
__device__ int   g_idx[NP*KK];
__device__ float g_xx[NP];
__device__ ulonglong2 g_w1p[131072];         // fp32-packed W1 pairs, per-layer offsets
__device__ float4     g_wdp[12288];          // packed (W2 - W1), per-layer offsets
__device__ uint2 g_wp2[256*64];              // W1 split (hi,lo) L3, [o][c2]
__device__ uint2 g_hp[NP*64];                // h split (hi,lo) L2-out, [p][c2]
__device__ float g_base[(size_t)NP*256];     // (W2-W1)*ctr per (p,o), L3
__device__ float g_fused[(size_t)NP*512];
__device__ uint32_t g_fh[(size_t)NP*256];    // normalized fused bf16-hi pairs
__device__ uint32_t g_fl[(size_t)NP*256];    // normalized fused bf16-lo pairs
__device__ float g_psum[(size_t)NP*256];     // transposed: [o*P + p]
__device__ float g_pssq[(size_t)NP*256];
__device__ float g_scale[1024];
__device__ float g_shift[1024];
__device__ __nv_bfloat16 g_bh[1024*512];     // Wf split hi
__device__ __nv_bfloat16 g_bl[1024*512];     // Wf split lo

__device__ __forceinline__ void fma2(unsigned long long& d,
                                     unsigned long long a, unsigned long long b) {
    asm("fma.rn.f32x2 %0, %1, %2, %0;" : "+l"(d) : "l"(a), "l"(b));
}
__device__ __forceinline__ unsigned long long pack2(float lo, float hi) {
    unsigned long long r;
    asm("mov.b64 %0, {%1, %2};" : "=l"(r) : "f"(lo), "f"(hi));
    return r;
}
__device__ __forceinline__ void unpack2(float& lo, float& hi, unsigned long long v) {
    asm("mov.b64 {%0, %1}, %2;" : "=f"(lo), "=f"(hi) : "l"(v));
}
__device__ __forceinline__ uint32_t packbf2(float a, float b) {
    __nv_bfloat162 p;
    p.x = __float2bfloat16(a);
    p.y = __float2bfloat16(b);
    return *(uint32_t*)&p;
}
__device__ __forceinline__ uint32_t mono_u32(float f) {
    uint32_t b = __float_as_uint(f);
    return (b & 0x80000000u) ? ~b : (b | 0x80000000u);   // exact order-preserving
}
// HMMA m16n8k16 bf16 -> fp32 accumulate
__device__ __forceinline__ void mma16816(float* c, const uint32_t* a, const uint32_t* b) {
    asm volatile("mma.sync.aligned.m16n8k16.row.col.f32.bf16.bf16.f32 "
        "{%0,%1,%2,%3}, {%4,%5,%6,%7}, {%8,%9}, {%0,%1,%2,%3};"
        : "+f"(c[0]), "+f"(c[1]), "+f"(c[2]), "+f"(c[3])
        : "r"(a[0]), "r"(a[1]), "r"(a[2]), "r"(a[3]), "r"(b[0]), "r"(b[1]));
}

// layer offsets into g_wdp / g_w1p (entries)
#define WOFF0 0
#define WOFF1 64
#define WOFF2 1088
#define WOFF3 3136

// -------- unified prep: wtrans(all) + wsplit + wfsplit + xx(x, exact tree) -----
__global__ void prep_kernel(const float* __restrict__ W0, const float* __restrict__ W1,
                            const float* __restrict__ W2, const float* __restrict__ W3,
                            const float* __restrict__ Wf, const float* __restrict__ x) {
    int i = blockIdx.x*256 + threadIdx.x;
    if (i < 11328) {
        const float* W; int C, OUT, base;
        if (i < 64)        { W = W0; C = 3;   OUT = 64;  base = 0;    }
        else if (i < 1088) { W = W1; C = 64;  OUT = 64;  base = 64;   }
        else if (i < 3136) { W = W2; C = 64;  OUT = 128; base = 1088; }
        else               { W = W3; C = 128; OUT = 256; base = 3136; }
        int li = i - base;
        int o = li % OUT, c4 = li / OUT;
        float w1[4], wd[4];
        #pragma unroll
        for (int j = 0; j < 4; j++) {
            int c = c4*4 + j;
            if (c < C) {
                float a = W[(size_t)o*2*C + c];
                float b2 = W[(size_t)o*2*C + C + c];
                w1[j] = a; wd[j] = b2 - a;
            } else { w1[j] = 0.f; wd[j] = 0.f; }
        }
        ulonglong2 wp;
        wp.x = pack2(w1[0], w1[1]);
        wp.y = pack2(w1[2], w1[3]);
        g_w1p[i] = wp;
        g_wdp[i] = make_float4(wd[0], wd[1], wd[2], wd[3]);
    } else if (i < 27712) {
        int li = i - 11328;                 // wsplit L3: OUT=256, C=128, C2=64
        int o = li >> 6, c2 = li & 63;
        float w0 = W3[(size_t)o*256 + 2*c2];
        float w1 = W3[(size_t)o*256 + 2*c2 + 1];
        __nv_bfloat16 h0 = __float2bfloat16(w0);
        __nv_bfloat16 h1 = __float2bfloat16(w1);
        uint2 v;
        v.x = ((uint32_t)*(uint16_t*)&h1 << 16) | (uint32_t)*(uint16_t*)&h0;
        v.y = packbf2(w0 - __bfloat162float(h0), w1 - __bfloat162float(h1));
        g_wp2[li] = v;
    } else if (i < 552000) {
        int li = i - 27712;                 // wfsplit
        float w = Wf[li];
        __nv_bfloat16 h = __float2bfloat16(w);
        g_bh[li] = h;
        g_bl[li] = __float2bfloat16(w - __bfloat162float(h));
    } else if (i < 560192) {
        int p = i - 552000;                 // xx for input layer
        float x0 = x[p*3], x1 = x[p*3+1], x2 = x[p*3+2];
        // exact replica of the 64-thread tree for C=3: (x0^2 + x2^2) + x1^2
        g_xx[p] = __fadd_rn(__fadd_rn(__fmul_rn(x0, x0), __fmul_rn(x2, x2)),
                            __fmul_rn(x1, x1));
    }
}

// ----- neg_dist: 64x64 register-tiled GEMM + f32x2; stores monotone uints ------
__global__ void __launch_bounds__(256) negdist_kernel(const float* __restrict__ h, int C) {
    __shared__ float As[16][68];
    __shared__ float Bs[16][68];
    int b  = blockIdx.z;
    int n0 = blockIdx.y * 64, m0 = blockIdx.x * 64;
    int tid = threadIdx.x;
    int tx = tid & 15, ty = tid >> 4;
    unsigned long long acc[4][2];
    #pragma unroll
    for (int i = 0; i < 4; i++) { acc[i][0] = 0ull; acc[i][1] = 0ull; }

    for (int c0 = 0; c0 < C; c0 += 16) {
        #pragma unroll
        for (int r = 0; r < 4; r++) {
            int idx = tid + r*256;
            int cc = idx & 15, n = idx >> 4;
            int c = c0 + cc;
            As[cc][n] = (c < C) ? h[((size_t)(b*NN) + n0 + n)*C + c] : 0.f;
            Bs[cc][n] = (c < C) ? h[((size_t)(b*NN) + m0 + n)*C + c] : 0.f;
        }
        __syncthreads();
        #pragma unroll
        for (int kk = 0; kk < 16; kk++) {
            float4 a = *(const float4*)&As[kk][ty*4];
            ulonglong2 bb = *(const ulonglong2*)&Bs[kk][tx*4];
            unsigned long long a0 = pack2(a.x, a.x);
            unsigned long long a1 = pack2(a.y, a.y);
            unsigned long long a2 = pack2(a.z, a.z);
            unsigned long long a3 = pack2(a.w, a.w);
            fma2(acc[0][0], a0, bb.x); fma2(acc[0][1], a0, bb.y);
            fma2(acc[1][0], a1, bb.x); fma2(acc[1][1], a1, bb.y);
            fma2(acc[2][0], a2, bb.x); fma2(acc[2][1], a2, bb.y);
            fma2(acc[3][0], a3, bb.x); fma2(acc[3][1], a3, bb.y);
        }
        __syncthreads();
    }
    #pragma unroll
    for (int i = 0; i < 4; i++) {
        int n = n0 + ty*4 + i;
        float xn = g_xx[b*NN + n];
        #pragma unroll
        for (int jp = 0; jp < 2; jp++) {
            float lo, hi;
            unpack2(lo, hi, acc[i][jp]);
            int m = m0 + tx*4 + jp*2;
            float d0 = 2.f*lo - xn - g_xx[b*NN + m];
            float d1 = 2.f*hi - xn - g_xx[b*NN + m + 1];
            uint2 dv;
            dv.x = mono_u32(d0);
            dv.y = mono_u32(d1);
            *(uint2*)&g_dist[((size_t)(b*NN) + n)*NN + m] = dv;
        }
    }
}

// ------- top-k: warp/point, lazy per-lane top-4 + redux.sync -------------------
// Selection order: value desc, index asc -- identical to verified kernel.
__global__ void topk_kernel() {
    int lane = threadIdx.x & 31;
    int p = blockIdx.x * 8 + (threadIdx.x >> 5);
    const uint4* row = (const uint4*)(g_dist + (size_t)p*NN) + lane*8;
    uint32_t u[32];
    #pragma unroll
    for (int j = 0; j < 8; j++) {
        uint4 v = row[j];
        u[j*4+0] = v.x; u[j*4+1] = v.y; u[j*4+2] = v.z; u[j*4+3] = v.w;
    }
    // per-lane sorted top-4 (strict >: earliest index kept on ties)
    uint32_t m0 = 0u, m1 = 0u, m2 = 0u, m3 = 0u;
    int i0 = 0, i1 = 0, i2 = 0, i3 = 0;
    #pragma unroll
    for (int j = 0; j < 32; j++) {
        uint32_t x = u[j];
        if (x > m0)      { m3=m2; i3=i2; m2=m1; i2=i1; m1=m0; i1=i0; m0=x; i0=j; }
        else if (x > m1) { m3=m2; i3=i2; m2=m1; i2=i1; m1=x; i1=j; }
        else if (x > m2) { m3=m2; i3=i2; m2=x; i2=j; }
        else if (x > m3) { m3=x; i3=j; }
    }
    int nv = 4;

    for (int k = 0; k < KK; k++) {
        uint32_t um = __reduce_max_sync(0xffffffffu, m0);
        int gi = (m0 == um) ? (lane*32 + i0) : 0x7FFFFFFF;
        int gmin = __reduce_min_sync(0xffffffffu, gi);
        if (lane == 0) g_idx[p*KK + k] = gmin;
        if (gi == gmin) {
            u[i0] = 0u;
            nv--;
            if (nv == 0) {
                uint32_t a0 = 0u, a1 = 0u, a2 = 0u, a3 = 0u;
                int b0 = 0, b1 = 0, b2 = 0, b3 = 0;
                #pragma unroll
                for (int j = 0; j < 32; j++) {
                    uint32_t x = u[j];
                    if (x > a0)      { a3=a2; b3=b2; a2=a1; b2=b1; a1=a0; b1=b0; a0=x; b0=j; }
                    else if (x > a1) { a3=a2; b3=b2; a2=a1; b2=b1; a1=x; b1=j; }
                    else if (x > a2) { a3=a2; b3=b2; a2=x; b2=j; }
                    else if (x > a3) { a3=x; b3=j; }
                }
                m0=a0; i0=b0; m1=a1; i1=b1; m2=a2; i2=b2; m3=a3; i3=b3;
                nv = 4;
            } else {
                m0=m1; i0=i1; m1=m2; i1=i2; m2=m3; i2=i3; m3=0u;
            }
        }
    }
}

// ------- base = (W2-W1)*ctr (L3): 8-point tiled GEMM ---------------------------
__global__ void __launch_bounds__(256) base_kernel(const float* __restrict__ h) {
    __shared__ float4 sctr[8][32];
    int tid = threadIdx.x;
    int pbase = blockIdx.x * 8;
    sctr[tid >> 5][tid & 31] =
        ((const float4*)h)[(size_t)(pbase + (tid >> 5))*32 + (tid & 31)];
    __syncthreads();
    int o = tid;
    float acc[8];
    #pragma unroll
    for (int pt = 0; pt < 8; pt++) acc[pt] = 0.f;
    for (int c4 = 0; c4 < 32; c4++) {
        float4 w = g_wdp[WOFF3 + c4*256 + o];
        #pragma unroll
        for (int pt = 0; pt < 8; pt++) {
            float4 cv = sctr[pt][c4];
            acc[pt] += w.x*cv.x + w.y*cv.y + w.z*cv.z + w.w*cv.w;
        }
    }
    #pragma unroll
    for (int pt = 0; pt < 8; pt++)
        g_base[(size_t)(pbase + pt)*256 + o] = acc[pt];
}

// ------- edge conv (layers 0-2): exact fp32, grouped multi-point blocks -------
__global__ void edgeconv_kernel(const float* __restrict__ h, int C, int Cp,
                                int lc, int OUT, int foff, int G, int half,
                                int wOff) {
    extern __shared__ float sm[];
    __shared__ int nb[8*KK];
    int tid = threadIdx.x;
    int gidx = tid / half;
    int t = tid - gidx*half;
    int p = blockIdx.x * G + gidx;
    int b = p >> 10;
    float* ctr  = sm + gidx * (Cp + KK*Cp);
    float* feat = ctr + Cp;

    for (int t2 = tid; t2 < G*KK; t2 += blockDim.x)
        nb[t2] = g_idx[(blockIdx.x*G + t2/KK)*KK + (t2 - (t2/KK)*KK)];
    for (int c = t; c < Cp; c += half)
        ctr[c] = (c < C) ? h[(size_t)p*C + c] : 0.f;
    __syncthreads();
    int mask = Cp - 1;
    for (int tt = t; tt < KK*Cp; tt += half) {
        int k = tt >> lc, c = tt & mask;
        feat[tt] = (c < C) ? h[((size_t)((b << 10) + nb[gidx*KK + k]))*C + c] : 0.f;
    }
    __syncthreads();

    int o0 = t, o1 = t + half;
    int C4 = Cp >> 2;
    const float4* c4p = (const float4*)ctr;
    float base0 = 0.f, base1 = 0.f;
    for (int c4 = 0; c4 < C4; c4++) {
        float4 cv = c4p[c4];
        float4 w0 = g_wdp[wOff + c4*OUT + o0];
        float4 w1 = g_wdp[wOff + c4*OUT + o1];
        base0 += w0.x*cv.x + w0.y*cv.y + w0.z*cv.z + w0.w*cv.w;
        base1 += w1.x*cv.x + w1.y*cv.y + w1.z*cv.z + w1.w*cv.w;
    }
    const ulonglong2* f2 = (const ulonglong2*)feat;
    float mx0=-1e30f, s0=0.f, q0=0.f;
    float mx1=-1e30f, s1=0.f, q1=0.f;
    #pragma unroll
    for (int kc = 0; kc < KK; kc += 10) {
        unsigned long long a0[10], a1[10];
        #pragma unroll
        for (int k = 0; k < 10; k++) { a0[k] = 0ull; a1[k] = 0ull; }
        for (int c4 = 0; c4 < C4; c4++) {
            ulonglong2 w0 = g_w1p[wOff + c4*OUT + o0];
            ulonglong2 w1 = g_w1p[wOff + c4*OUT + o1];
            #pragma unroll
            for (int k = 0; k < 10; k++) {
                ulonglong2 fv = f2[(kc+k)*C4 + c4];
                fma2(a0[k], w0.x, fv.x); fma2(a0[k], w0.y, fv.y);
                fma2(a1[k], w1.x, fv.x); fma2(a1[k], w1.y, fv.y);
            }
        }
        #pragma unroll
        for (int k = 0; k < 10; k++) {
            float lo, hi;
            unpack2(lo, hi, a0[k]);
            float y = base0 + lo + hi;
            mx0 = fmaxf(mx0, y); s0 += y; q0 += y*y;
            unpack2(lo, hi, a1[k]);
            y = base1 + lo + hi;
            mx1 = fmaxf(mx1, y); s1 += y; q1 += y*y;
        }
    }
    g_fused[(size_t)p*512 + foff + o0] = mx0;
    g_fused[(size_t)p*512 + foff + o1] = mx1;
    g_psum[(size_t)o0*NP + p] = s0; g_pssq[(size_t)o0*NP + p] = q0;
    g_psum[(size_t)o1*NP + p] = s1; g_pssq[(size_t)o1*NP + p] = q1;
}

// ------- edge conv L3 via HMMA 2-way bf16 split (3 products) ------------------
__global__ void __launch_bounds__(256) edgemma_kernel(
    int C2, int OUT, int foff, int nchunks)
{
    __shared__ uint32_t sA[2][128*18];
    __shared__ uint32_t sB[2][128*18];
    __shared__ int nb[80];

    int tid = threadIdx.x, wid = tid >> 5, lane = tid & 31;
    int g = lane >> 2, t = lane & 3;
    int wm = wid >> 2, wn = wid & 3;
    int pbase = blockIdx.x * 4;
    int obase = blockIdx.y * 128;
    int batch_off = (pbase >> 10) << 10;

    if (tid < 80) nb[tid] = g_idx[(pbase + tid/20)*KK + (tid - (tid/20)*20)];

    float acc[4][4][4];
    #pragma unroll
    for (int mi = 0; mi < 4; mi++)
        #pragma unroll
        for (int ni = 0; ni < 4; ni++)
            #pragma unroll
            for (int j = 0; j < 4; j++) acc[mi][ni][j] = 0.f;

    __syncthreads();

    for (int chunk = 0; chunk < nchunks; chunk++) {
        if (chunk > 0) __syncthreads();
        for (int i = tid; i < 2048; i += 256) {
            int row = i >> 4, kp = i & 15;
            int k = row & 31, lp = row >> 5;
            int c2 = chunk*16 + kp;
            uint2 v = make_uint2(0u, 0u);
            if (k < KK && c2 < C2)
                v = g_hp[(size_t)(batch_off + nb[lp*20 + k])*C2 + c2];
            sA[0][row*18 + kp] = v.x;
            sA[1][row*18 + kp] = v.y;
        }
        for (int i = tid; i < 2048; i += 256) {
            int row = i >> 4, kp = i & 15;
            int c2 = chunk*16 + kp;
            uint2 v = make_uint2(0u, 0u);
            if (c2 < C2)
                v = g_wp2[(size_t)(obase + row)*C2 + c2];
            sB[0][row*18 + kp] = v.x;
            sB[1][row*18 + kp] = v.y;
        }
        __syncthreads();
        #pragma unroll
        for (int ks = 0; ks < 2; ks++) {
            int kp0 = ks * 8;
            uint32_t af[2][4][4];
            #pragma unroll
            for (int a = 0; a < 2; a++)
                #pragma unroll
                for (int mi = 0; mi < 4; mi++) {
                    int r = wm*64 + mi*16 + g;
                    af[a][mi][0] = sA[a][r*18 + kp0 + t];
                    af[a][mi][1] = sA[a][(r+8)*18 + kp0 + t];
                    af[a][mi][2] = sA[a][r*18 + kp0 + 4 + t];
                    af[a][mi][3] = sA[a][(r+8)*18 + kp0 + 4 + t];
                }
            uint32_t bf[2][4][2];
            #pragma unroll
            for (int a = 0; a < 2; a++)
                #pragma unroll
                for (int ni = 0; ni < 4; ni++) {
                    int n = wn*32 + ni*8 + g;
                    bf[a][ni][0] = sB[a][n*18 + kp0 + t];
                    bf[a][ni][1] = sB[a][n*18 + kp0 + 4 + t];
                }
            #pragma unroll
            for (int mi = 0; mi < 4; mi++)
                #pragma unroll
                for (int ni = 0; ni < 4; ni++) {
                    mma16816(acc[mi][ni], af[0][mi], bf[0][ni]);
                    mma16816(acc[mi][ni], af[0][mi], bf[1][ni]);
                    mma16816(acc[mi][ni], af[1][mi], bf[0][ni]);
                }
        }
    }

    #pragma unroll
    for (int half = 0; half < 2; half++) {
        int p = pbase + wm*2 + half;
        #pragma unroll
        for (int ni = 0; ni < 4; ni++) {
            #pragma unroll
            for (int j = 0; j < 2; j++) {
                float v0 = acc[half*2][ni][j];
                float v1 = acc[half*2][ni][j+2];
                float v2 = acc[half*2+1][ni][j];
                bool ok2 = (g < 4);
                float mx = fmaxf(v0, v1);
                if (ok2) mx = fmaxf(mx, v2);
                float s = v0 + v1 + (ok2 ? v2 : 0.f);
                float q = v0*v0 + v1*v1 + (ok2 ? v2*v2 : 0.f);
                #pragma unroll
                for (int off = 4; off <= 16; off <<= 1) {
                    mx = fmaxf(mx, __shfl_xor_sync(0xffffffffu, mx, off));
                    s += __shfl_xor_sync(0xffffffffu, s, off);
                    q += __shfl_xor_sync(0xffffffffu, q, off);
                }
                if (g == 0) {
                    int o = obase + wn*32 + ni*8 + t*2 + j;
                    float b = g_base[(size_t)p*256 + o];
                    g_fused[(size_t)p*512 + foff + o] = mx + b;
                    g_psum[(size_t)o*NP + p] = s + 20.f*b;
                    g_pssq[(size_t)o*NP + p] = q + 2.f*b*s + 20.f*b*b;
                }
            }
        }
    }
}

// ---------------- per-channel BN stats (verified 256-thread version) -----------
__global__ void chanstats_kernel(const float* __restrict__ g,
                                 const float* __restrict__ bta,
                                 int P, float invM) {
    int o = blockIdx.x;
    __shared__ float ssum[256], ssq[256];
    const float* ps = g_psum + (size_t)o*P;
    const float* pq = g_pssq + (size_t)o*P;
    float s = 0.f, q = 0.f;
    for (int i = threadIdx.x; i < P; i += 256) { s += ps[i]; q += pq[i]; }
    ssum[threadIdx.x] = s; ssq[threadIdx.x] = q;
    __syncthreads();
    for (int st = 128; st > 0; st >>= 1) {
        if (threadIdx.x < st) {
            ssum[threadIdx.x] += ssum[threadIdx.x + st];
            ssq [threadIdx.x] += ssq [threadIdx.x + st];
        }
        __syncthreads();
    }
    if (threadIdx.x == 0) {
        float mean = ssum[0] * invM;
        float var  = ssq[0] * invM - mean*mean;
        float sc   = rsqrtf(var + 1e-5f) * g[o];
        g_scale[o] = sc;
        g_shift[o] = bta[o] - mean * sc;
    }
}

// -- BN + LeakyReLU (grouped blocks); per-point reduction tree is bit-identical --
__global__ void normedge_kernel(int OUT, int foff, float* __restrict__ hnext,
                                int wantnext, int wantsplit, int G2) {
    __shared__ float sh[256];
    int tid = threadIdx.x;
    int gidx = tid / OUT;
    int o = tid - gidx*OUT;
    int p = blockIdx.x * G2 + gidx;
    float v = g_fused[(size_t)p*512 + foff + o] * g_scale[o] + g_shift[o];
    v = v > 0.f ? v : 0.2f*v;
    g_fused[(size_t)p*512 + foff + o] = v;
    float vo = __shfl_xor_sync(0xffffffffu, v, 1);   // o parity == lane parity (OUT%32==0)
    if (wantnext) hnext[(size_t)p*OUT + o] = v;
    if (!(o & 1)) {
        __nv_bfloat16 h0 = __float2bfloat16(v);
        __nv_bfloat16 h1 = __float2bfloat16(vo);
        uint32_t hi = ((uint32_t)*(uint16_t*)&h1 << 16) | (uint32_t)*(uint16_t*)&h0;
        uint32_t lo = packbf2(v - __bfloat162float(h0), vo - __bfloat162float(h1));
        size_t fidx = (size_t)p*256 + ((foff + o) >> 1);
        g_fh[fidx] = hi;
        g_fl[fidx] = lo;
        if (wantsplit) {
            uint2 hv; hv.x = hi; hv.y = lo;
            g_hp[(size_t)p*(OUT/2) + (o >> 1)] = hv;
        }
    }
    sh[tid] = v*v;
    __syncthreads();
    for (int st = OUT >> 1; st > 0; st >>= 1) {
        if (o < st) sh[tid] += sh[tid + st];
        __syncthreads();
    }
    if (o == 0 && wantnext) g_xx[p] = sh[tid];
}

// ---------------- final linear via HMMA bf16-split (A pre-split) ---------------
__global__ void __launch_bounds__(256) finalmma_kernel(float* __restrict__ out) {
    __shared__ uint32_t sAh[128*18], sAl[128*18];
    __shared__ uint32_t sBh[128*18], sBl[128*18];
    __shared__ float red[2][2][128];

    int tid = threadIdx.x, wid = tid >> 5, lane = tid & 31;
    int g = lane >> 2, t = lane & 3;
    int wm = wid >> 2, wn = wid & 3;
    int pb = blockIdx.x, ob = blockIdx.y;
    int pbase = pb * 128, obase = ob * 128;

    float acc[4][4][4];
    #pragma unroll
    for (int mi = 0; mi < 4; mi++)
        #pragma unroll
        for (int ni = 0; ni < 4; ni++)
            #pragma unroll
            for (int j = 0; j < 4; j++) acc[mi][ni][j] = 0.f;

    const uint32_t* bh2 = (const uint32_t*)g_bh;
    const uint32_t* bl2 = (const uint32_t*)g_bl;

    for (int c0 = 0; c0 < 512; c0 += 32) {
        __syncthreads();
        #pragma unroll
        for (int i = tid; i < 2048; i += 256) {
            int row = i >> 4, kp = i & 15;
            size_t ai = (size_t)(pbase + row)*256 + (c0 >> 1) + kp;
            sAh[row*18 + kp] = g_fh[ai];
            sAl[row*18 + kp] = g_fl[ai];
            size_t gi = (size_t)(obase + row)*256 + (c0 >> 1) + kp;
            sBh[row*18 + kp] = bh2[gi];
            sBl[row*18 + kp] = bl2[gi];
        }
        __syncthreads();
        #pragma unroll
        for (int ks = 0; ks < 2; ks++) {
            int kp0 = ks * 8;
            uint32_t ah[4][4], al[4][4];
            #pragma unroll
            for (int mi = 0; mi < 4; mi++) {
                int r = wm*64 + mi*16 + g;
                ah[mi][0] = sAh[r*18 + kp0 + t];
                ah[mi][1] = sAh[(r+8)*18 + kp0 + t];
                ah[mi][2] = sAh[r*18 + kp0 + 4 + t];
                ah[mi][3] = sAh[(r+8)*18 + kp0 + 4 + t];
                al[mi][0] = sAl[r*18 + kp0 + t];
                al[mi][1] = sAl[(r+8)*18 + kp0 + t];
                al[mi][2] = sAl[r*18 + kp0 + 4 + t];
                al[mi][3] = sAl[(r+8)*18 + kp0 + 4 + t];
            }
            uint32_t bh[4][2], bl[4][2];
            #pragma unroll
            for (int ni = 0; ni < 4; ni++) {
                int n = wn*32 + ni*8 + g;
                bh[ni][0] = sBh[n*18 + kp0 + t];
                bh[ni][1] = sBh[n*18 + kp0 + 4 + t];
                bl[ni][0] = sBl[n*18 + kp0 + t];
                bl[ni][1] = sBl[n*18 + kp0 + 4 + t];
            }
            #pragma unroll
            for (int mi = 0; mi < 4; mi++)
                #pragma unroll
                for (int ni = 0; ni < 4; ni++) {
                    mma16816(acc[mi][ni], ah[mi], bh[ni]);
                    mma16816(acc[mi][ni], ah[mi], bl[ni]);
                    mma16816(acc[mi][ni], al[mi], bh[ni]);
                }
        }
    }

    #pragma unroll
    for (int ni = 0; ni < 4; ni++) {
        float s0 = 0.f, s1 = 0.f, q0 = 0.f, q1 = 0.f;
        #pragma unroll
        for (int mi = 0; mi < 4; mi++) {
            float* a = acc[mi][ni];
            int row = pbase + wm*64 + mi*16 + g;
            int col = obase + wn*32 + ni*8 + t*2;
            *(float2*)&out[(size_t)row*1024 + col]     = make_float2(a[0], a[1]);
            *(float2*)&out[(size_t)(row+8)*1024 + col] = make_float2(a[2], a[3]);
            s0 += a[0] + a[2]; s1 += a[1] + a[3];
            q0 += a[0]*a[0] + a[2]*a[2];
            q1 += a[1]*a[1] + a[3]*a[3];
        }
        #pragma unroll
        for (int off = 4; off < 32; off <<= 1) {
            s0 += __shfl_xor_sync(0xffffffffu, s0, off);
            s1 += __shfl_xor_sync(0xffffffffu, s1, off);
            q0 += __shfl_xor_sync(0xffffffffu, q0, off);
            q1 += __shfl_xor_sync(0xffffffffu, q1, off);
        }
        if (g == 0) {
            int colw = wn*32 + ni*8 + t*2;
            red[wm][0][colw]   = s0;
            red[wm][0][colw+1] = s1;
            red[wm][1][colw]   = q0;
            red[wm][1][colw+1] = q1;
        }
    }
    __syncthreads();
    if (tid < 128) {
        float s = red[0][0][tid] + red[1][0][tid];
        float q = red[0][1][tid] + red[1][1][tid];
        g_psum[(size_t)(obase + tid)*64 + pb] = s;
        g_pssq[(size_t)(obase + tid)*64 + pb] = q;
    }
}

// ---------------- final BN + LeakyReLU in place (float4) -----------------------
__global__ void normout_kernel(float* __restrict__ out) {
    int i = blockIdx.x*256 + threadIdx.x;
    if (i >= NP*256) return;
    int ob = (i & 255) * 4;
    float4 v = ((float4*)out)[i];
    v.x = v.x * g_scale[ob+0] + g_shift[ob+0];
    v.y = v.y * g_scale[ob+1] + g_shift[ob+1];
    v.z = v.z * g_scale[ob+2] + g_shift[ob+2];
    v.w = v.w * g_scale[ob+3] + g_shift[ob+3];
    v.x = v.x > 0.f ? v.x : 0.2f*v.x;
    v.y = v.y > 0.f ? v.y : 0.2f*v.y;
    v.z = v.z > 0.f ? v.z : 0.2f*v.z;
    v.w = v.w > 0.f ? v.w : 0.2f*v.w;
    ((float4*)out)[i] = v;
}

// ------------------------------- launcher -------------------------------------
extern "C" void kernel_launch(void* const* d_in, const int* in_sizes, int n_in,
                              void* d_out, int out_size) {
    (void)in_sizes; (void)n_in; (void)out_size;
    const float* x  = (const float*)d_in[0];
    const float* W[4]  = {(const float*)d_in[1],  (const float*)d_in[4],
                          (const float*)d_in[7],  (const float*)d_in[10]};
    const float* ga[4] = {(const float*)d_in[2],  (const float*)d_in[5],
                          (const float*)d_in[8],  (const float*)d_in[11]};
    const float* bt[4] = {(const float*)d_in[3],  (const float*)d_in[6],
                          (const float*)d_in[9],  (const float*)d_in[12]};
    const float* Wf = (const float*)d_in[13];
    const float* gf = (const float*)d_in[14];
    const float* bf = (const float*)d_in[15];
    float* out = (float*)d_out;

    float *h1, *h2;
    cudaGetSymbolAddress((void**)&h1, g_h1);
    cudaGetSymbolAddress((void**)&h2, g_h2);
    float* hn[2] = {h1, h2};

    const int Cs[4]     = {3, 64, 64, 128};
    const int Cps[4]    = {4, 64, 64, 128};
    const int lcs[4]    = {2, 6, 6, 7};
    const int OUTs[4]   = {64, 64, 128, 256};
    const int foffs[4]  = {0, 64, 128, 256};
    const int Gs[4]     = {8, 8, 4, 0};
    const int G2s[4]    = {4, 4, 2, 1};
    const int wOffs[4]  = {WOFF0, WOFF1, WOFF2, WOFF3};

    prep_kernel<<<(560192 + 255)/256, 256>>>(W[0], W[1], W[2], W[3], Wf, x);

    const float* hcur = x;
    for (int i = 0; i < 4; i++) {
        int C = Cs[i], Cp = Cps[i], OUT = OUTs[i];
        negdist_kernel<<<dim3(NN/64, NN/64, BB), 256>>>(hcur, C);
        topk_kernel<<<NP/8, 256>>>();
        if (i < 3) {
            int G = Gs[i], half = OUT/2;
            size_t smem = (size_t)G * (Cp + KK*Cp) * sizeof(float);
            edgeconv_kernel<<<NP/G, G*half, smem>>>(hcur, C, Cp, lcs[i], OUT,
                                                    foffs[i], G, half, wOffs[i]);
        } else {
            base_kernel<<<NP/8, 256>>>(hcur);
            edgemma_kernel<<<dim3(NP/4, 2), 256>>>(64, OUT, foffs[i], 4);
        }
        chanstats_kernel<<<OUT, 256>>>(ga[i], bt[i], NP, 1.f/((float)NP*KK));
        int wantnext = (i < 3) ? 1 : 0;
        int wantsplit = (i == 2) ? 1 : 0;
        int G2 = G2s[i];
        normedge_kernel<<<NP/G2, G2*OUT>>>(OUT, foffs[i], hn[i & 1],
                                           wantnext, wantsplit, G2);
        hcur = hn[i & 1];
    }

    finalmma_kernel<<<dim3(64, 8), 256>>>(out);
    chanstats_kernel<<<1024, 256>>>(gf, bf, 64, 1.f/(float)NP);
    normout_kernel<<<(NP*256 + 255)/256, 256>>>(out);
}